// round 3
// baseline (speedup 1.0000x reference)
#include <cuda_runtime.h>
#include <math.h>

#define T_LEN 256
#define B_SZ  32
#define G4    1024
#define D_IN  768
#define D_L   512
#define NROWS 8192
#define XZS   (NROWS * G4)

__device__ float g_xz[2 * XZS];        // per-dir [b*T+t][1024]
__device__ float g_h [NROWS * D_L];    // [b*T+t][512] = concat(hf,hb)
__device__ float g_hc[NROWS * 1024];   // [row][0:512]=h, [512:1024]=ctx
__device__ float g_sq[NROWS * 10];
__device__ float g_sk[NROWS * 10];
__device__ unsigned g_bar_count, g_bar_gen;

__device__ __forceinline__ unsigned ld_acq(unsigned* p) {
    unsigned v;
    asm volatile("ld.acquire.gpu.u32 %0, [%1];" : "=r"(v) : "l"(p) : "memory");
    return v;
}

__device__ __forceinline__ void grid_sync() {
    __syncthreads();
    if (threadIdx.x == 0) {
        unsigned gen = ld_acq(&g_bar_gen);
        __threadfence();
        if (atomicAdd(&g_bar_count, 1u) == 127u) {
            g_bar_count = 0u;
            __threadfence();
            atomicAdd(&g_bar_gen, 1u);
        } else {
            while (ld_acq(&g_bar_gen) == gen) { }
        }
        __threadfence();
    }
    __syncthreads();
}

__device__ __forceinline__ float sigf(float x) {
    return fmaf(0.5f, tanhf(0.5f * x), 0.5f);
}

// ---- generic GEMM: C[m][n] = A[m][:] . W[n][:] + bias[n] ; 128x128 tiles ----
__global__ __launch_bounds__(256) void k_gemm(const float* __restrict__ A, int Kdim,
                                              const float* __restrict__ W,
                                              const float* __restrict__ bias,
                                              float* __restrict__ C, int ldc) {
    __shared__ float As[8][128], Bs[8][128];
    int tid = threadIdx.x;
    int m0 = blockIdx.y * 128, n0 = blockIdx.x * 128;
    int ar = tid >> 1, ak = (tid & 1) * 4;
    const float* Arow = A + (size_t)(m0 + ar) * Kdim;
    const float* Brow = W + (size_t)(n0 + ar) * Kdim;
    int tx = tid & 15, ty = tid >> 4;
    float acc[8][8];
#pragma unroll
    for (int i = 0; i < 8; i++)
#pragma unroll
        for (int j = 0; j < 8; j++) acc[i][j] = 0.f;

    for (int k0 = 0; k0 < Kdim; k0 += 8) {
        float4 av = *(const float4*)(Arow + k0 + ak);
        float4 bv = *(const float4*)(Brow + k0 + ak);
        __syncthreads();
        As[ak + 0][ar] = av.x; As[ak + 1][ar] = av.y;
        As[ak + 2][ar] = av.z; As[ak + 3][ar] = av.w;
        Bs[ak + 0][ar] = bv.x; Bs[ak + 1][ar] = bv.y;
        Bs[ak + 2][ar] = bv.z; Bs[ak + 3][ar] = bv.w;
        __syncthreads();
#pragma unroll
        for (int kk = 0; kk < 8; kk++) {
            float a[8], b[8];
            *(float4*)(a)     = *(const float4*)&As[kk][ty * 8];
            *(float4*)(a + 4) = *(const float4*)&As[kk][ty * 8 + 4];
            *(float4*)(b)     = *(const float4*)&Bs[kk][tx * 8];
            *(float4*)(b + 4) = *(const float4*)&Bs[kk][tx * 8 + 4];
#pragma unroll
            for (int i = 0; i < 8; i++)
#pragma unroll
                for (int j = 0; j < 8; j++) acc[i][j] = fmaf(a[i], b[j], acc[i][j]);
        }
    }
#pragma unroll
    for (int i = 0; i < 8; i++) {
        float* orow = C + (size_t)(m0 + ty * 8 + i) * ldc;
#pragma unroll
        for (int j = 0; j < 8; j++) {
            int nn = n0 + tx * 8 + j;
            orow[nn] = acc[i][j] + bias[nn];
        }
    }
}

// ---- persistent bidirectional LSTM: 128 blocks x 128 threads ----
__global__ __launch_bounds__(128) void k_lstm(const float* __restrict__ Whf,
                                              const float* __restrict__ Whb) {
    __shared__ float4 w4[16][65];   // 16 gate rows x 256 k
    __shared__ float4 h4[32][33];   // 32 batches x 128 k (half)
    __shared__ float  z_s[16 * 33];

    int tid = threadIdx.x, bi = blockIdx.x;
    int dir = bi >> 6, u0 = (bi & 63) * 4;
    const float* Whh = dir ? Whb : Whf;

    for (int i = tid; i < 16 * 64; i += 128) {
        int gl = i >> 6, kq = i & 63;           // gl = q*4+ul
        int q = gl >> 2, ul = gl & 3;
        w4[gl][kq] = *(const float4*)(Whh + (size_t)(q * 256 + u0 + ul) * 256 + kq * 4);
    }
    __syncthreads();

    int gp = tid >> 4, bp = tid & 15;
    int gA = gp * 2, gB = gA + 1, bB = bp + 16;
    int a_ul = tid & 3, a_b = tid >> 2;
    const float* xz = g_xz + (size_t)dir * XZS;
    float c_reg = 0.f;

    for (int s = 0; s < T_LEN; s++) {
        int t = dir ? (T_LEN - 1 - s) : s;
        const float* xzp = xz + (size_t)(a_b * T_LEN + t) * G4 + u0 + a_ul;
        float xzi = xzp[0], xzf = xzp[256], xzg = xzp[512], xzo = xzp[768];

        float a00 = 0.f, a01 = 0.f, a10 = 0.f, a11 = 0.f;
        if (s > 0) {
            int tp = dir ? (T_LEN - s) : (s - 1);
#pragma unroll
            for (int p = 0; p < 2; p++) {
                __syncthreads();
                for (int i = tid; i < 32 * 32; i += 128) {
                    int b = i >> 5, kq = i & 31;
                    h4[b][kq] = *(const float4*)(g_h + (size_t)(b * T_LEN + tp) * D_L +
                                                 dir * 256 + p * 128 + kq * 4);
                }
                __syncthreads();
#pragma unroll 8
                for (int kq = 0; kq < 32; kq++) {
                    float4 w0 = w4[gA][p * 32 + kq], w1 = w4[gB][p * 32 + kq];
                    float4 hA = h4[bp][kq], hB = h4[bB][kq];
                    a00 = fmaf(w0.x, hA.x, fmaf(w0.y, hA.y, fmaf(w0.z, hA.z, fmaf(w0.w, hA.w, a00))));
                    a01 = fmaf(w0.x, hB.x, fmaf(w0.y, hB.y, fmaf(w0.z, hB.z, fmaf(w0.w, hB.w, a01))));
                    a10 = fmaf(w1.x, hA.x, fmaf(w1.y, hA.y, fmaf(w1.z, hA.z, fmaf(w1.w, hA.w, a10))));
                    a11 = fmaf(w1.x, hB.x, fmaf(w1.y, hB.y, fmaf(w1.z, hB.z, fmaf(w1.w, hB.w, a11))));
                }
            }
        }
        z_s[gA * 33 + bp] = a00; z_s[gA * 33 + bB] = a01;
        z_s[gB * 33 + bp] = a10; z_s[gB * 33 + bB] = a11;
        __syncthreads();

        float zi = z_s[(0 + a_ul) * 33 + a_b] + xzi;
        float zf = z_s[(4 + a_ul) * 33 + a_b] + xzf;
        float zg = z_s[(8 + a_ul) * 33 + a_b] + xzg;
        float zo = z_s[(12 + a_ul) * 33 + a_b] + xzo;
        c_reg = fmaf(sigf(zf), c_reg, sigf(zi) * tanhf(zg));
        g_h[(size_t)(a_b * T_LEN + t) * D_L + dir * 256 + u0 + a_ul] = sigf(zo) * tanhf(c_reg);
        grid_sync();
    }
}

// ---- sq/sk projections + copy h into concat buffer ----
__global__ __launch_bounds__(256) void k_sqsk(const float* __restrict__ W1) {
    __shared__ float W1s[10 * 1024];
    int tid = threadIdx.x;
    for (int i = tid; i < 2560; i += 256) ((float4*)W1s)[i] = ((const float4*)W1)[i];
    __syncthreads();
    int w = tid >> 5, l = tid & 31;
    int row = blockIdx.x * 8 + w;
    const float4* hrow = (const float4*)(g_h + (size_t)row * D_L);
    float4* hcr = (float4*)(g_hc + (size_t)row * 1024);
    float4 hr[4];
#pragma unroll
    for (int j = 0; j < 4; j++) { hr[j] = hrow[l + 32 * j]; hcr[l + 32 * j] = hr[j]; }
#pragma unroll
    for (int xx = 0; xx < 10; xx++) {
        float sq = 0.f, sk = 0.f;
#pragma unroll
        for (int j = 0; j < 4; j++) {
            const float* wq = &W1s[xx * 1024 + (l + 32 * j) * 4];
            sq = fmaf(hr[j].x, wq[0], fmaf(hr[j].y, wq[1], fmaf(hr[j].z, wq[2], fmaf(hr[j].w, wq[3], sq))));
            sk = fmaf(hr[j].x, wq[512], fmaf(hr[j].y, wq[513], fmaf(hr[j].z, wq[514], fmaf(hr[j].w, wq[515], sk))));
        }
#pragma unroll
        for (int o = 16; o > 0; o >>= 1) {
            sq += __shfl_xor_sync(0xffffffffu, sq, o);
            sk += __shfl_xor_sync(0xffffffffu, sk, o);
        }
        if (l == 0) { g_sq[row * 10 + xx] = sq; g_sk[row * 10 + xx] = sk; }
    }
}

// ---- fused attention: scores -> softmax -> context ----
__global__ __launch_bounds__(256) void k_attn(const float* __restrict__ mask,
                                              const float* __restrict__ W2) {
    __shared__ float sc[32 * 257];
    __shared__ float sk_s[2560], sq_s[320], w2s[16], madd[256];
    int b = blockIdx.y, q0 = blockIdx.x * 32, tid = threadIdx.x;
    int row0 = b * T_LEN;

    for (int i = tid; i < 2560; i += 256) sk_s[i] = g_sk[row0 * 10 + i];
    for (int i = tid; i < 320; i += 256)  sq_s[i] = g_sq[(row0 + q0) * 10 + i];
    if (tid < 10) w2s[tid] = W2[tid];
    madd[tid] = (mask[row0 + tid] == 0.0f) ? -1e30f : 0.0f;
    __syncthreads();

    {
        float skr[10];
#pragma unroll
        for (int xx = 0; xx < 10; xx++) skr[xx] = sk_s[tid * 10 + xx];
        float mk = madd[tid];
        for (int q = 0; q < 32; q++) {
            float a = 0.f;
#pragma unroll
            for (int xx = 0; xx < 10; xx++)
                a = fmaf(w2s[xx], tanhf(sq_s[q * 10 + xx] + skr[xx]), a);
            sc[q * 257 + tid] = a + mk;
        }
    }
    __syncthreads();

    {   // softmax: warp w handles rows w, w+8, w+16, w+24
        int w = tid >> 5, l = tid & 31;
        for (int q = w; q < 32; q += 8) {
            float v[8], mx = -1e30f;
#pragma unroll
            for (int j = 0; j < 8; j++) { v[j] = sc[q * 257 + l + 32 * j]; mx = fmaxf(mx, v[j]); }
#pragma unroll
            for (int o = 16; o > 0; o >>= 1) mx = fmaxf(mx, __shfl_xor_sync(0xffffffffu, mx, o));
            float sum = 0.f;
#pragma unroll
            for (int j = 0; j < 8; j++) { v[j] = __expf(v[j] - mx); sum += v[j]; }
#pragma unroll
            for (int o = 16; o > 0; o >>= 1) sum += __shfl_xor_sync(0xffffffffu, sum, o);
            float inv = 1.0f / sum;
#pragma unroll
            for (int j = 0; j < 8; j++) sc[q * 257 + l + 32 * j] = v[j] * inv;
        }
    }
    __syncthreads();

    int qg = tid & 7, dq = tid >> 3;   // 4 q-rows, 16 d-floats each
    float4 acc[4][4];
#pragma unroll
    for (int j = 0; j < 4; j++)
#pragma unroll
        for (int c = 0; c < 4; c++) acc[j][c] = make_float4(0.f, 0.f, 0.f, 0.f);

    for (int k = 0; k < 256; k++) {
        const float4* hrow = (const float4*)(g_h + (size_t)(row0 + k) * D_L) + dq * 4;
        float4 hv[4];
#pragma unroll
        for (int c = 0; c < 4; c++) hv[c] = hrow[c];
#pragma unroll
        for (int j = 0; j < 4; j++) {
            float wq = sc[(qg * 4 + j) * 257 + k];
#pragma unroll
            for (int c = 0; c < 4; c++) {
                acc[j][c].x = fmaf(wq, hv[c].x, acc[j][c].x);
                acc[j][c].y = fmaf(wq, hv[c].y, acc[j][c].y);
                acc[j][c].z = fmaf(wq, hv[c].z, acc[j][c].z);
                acc[j][c].w = fmaf(wq, hv[c].w, acc[j][c].w);
            }
        }
    }
#pragma unroll
    for (int j = 0; j < 4; j++) {
        float4* orow = (float4*)(g_hc + (size_t)(row0 + q0 + qg * 4 + j) * 1024 + 512) + dq * 4;
#pragma unroll
        for (int c = 0; c < 4; c++) orow[c] = acc[j][c];
    }
}

extern "C" void kernel_launch(void* const* d_in, const int* in_sizes, int n_in,
                              void* d_out, int out_size) {
    const float* x     = (const float*)d_in[0];
    const float* mask  = (const float*)d_in[1];
    const float* Wih_f = (const float*)d_in[2];
    const float* Whh_f = (const float*)d_in[3];
    const float* b_f   = (const float*)d_in[4];
    const float* Wih_b = (const float*)d_in[5];
    const float* Whh_b = (const float*)d_in[6];
    const float* b_b   = (const float*)d_in[7];
    const float* W1    = (const float*)d_in[8];
    const float* W2    = (const float*)d_in[9];
    const float* W3    = (const float*)d_in[10];
    const float* b3    = (const float*)d_in[11];

    float* xzf;  cudaGetSymbolAddress((void**)&xzf, g_xz);
    float* xzb = xzf + XZS;
    float* out = (float*)d_out;

    k_gemm<<<dim3(8, 64), 256>>>(x, D_IN, Wih_f, b_f, xzf, G4);
    k_gemm<<<dim3(8, 64), 256>>>(x, D_IN, Wih_b, b_b, xzb, G4);
    k_lstm<<<128, 128>>>(Whh_f, Whh_b);
    k_sqsk<<<1024, 256>>>(W1);
    k_attn<<<dim3(8, 32), 256>>>(mask, W2);
    float* hc; cudaGetSymbolAddress((void**)&hc, g_hc);
    k_gemm<<<dim3(4, 64), 256>>>(hc, 1024, W3, b3, out, D_L);
}

// round 4
// speedup vs baseline: 1.0712x; 1.0712x over previous
#include <cuda_runtime.h>
#include <math.h>

#define T_LEN 256
#define B_SZ  32
#define G4    1024
#define D_IN  768
#define D_L   512
#define NROWS 8192
#define XZS   (NROWS * G4)

__device__ float g_xz[2 * XZS];        // per-dir [b*T+t][1024]
__device__ float g_h [NROWS * D_L];    // [b*T+t][512] = concat(hf,hb)
__device__ float g_hc[NROWS * 1024];   // [row][0:512]=h, [512:1024]=ctx
__device__ float g_sq[NROWS * 10];
__device__ float g_sk[NROWS * 10];
__device__ unsigned g_bar_count, g_bar_gen;

__device__ __forceinline__ unsigned ld_acq(unsigned* p) {
    unsigned v;
    asm volatile("ld.acquire.gpu.u32 %0, [%1];" : "=r"(v) : "l"(p) : "memory");
    return v;
}

__device__ __forceinline__ void grid_sync() {
    __syncthreads();
    if (threadIdx.x == 0) {
        unsigned gen = ld_acq(&g_bar_gen);
        __threadfence();
        if (atomicAdd(&g_bar_count, 1u) == 127u) {
            g_bar_count = 0u;
            __threadfence();
            atomicAdd(&g_bar_gen, 1u);
        } else {
            while (ld_acq(&g_bar_gen) == gen) { }
        }
        __threadfence();
    }
    __syncthreads();
}

__device__ __forceinline__ float sigf(float x) {
    return fmaf(0.5f, tanhf(0.5f * x), 0.5f);
}

// ---- double-buffered GEMM: C[m][n] = A[m][:] . W[n][:] + bias[n] ----
// blockIdx.z picks (W0,b0,C0) vs (W1,b1,C1). 128x128 tile, 8-k step.
__global__ __launch_bounds__(256) void k_gemm(const float* __restrict__ A, int Kdim,
                                              const float* __restrict__ W0,
                                              const float* __restrict__ b0,
                                              float* __restrict__ C0,
                                              const float* __restrict__ W1,
                                              const float* __restrict__ b1,
                                              float* __restrict__ C1, int ldc) {
    __shared__ float As[2][8][128], Bs[2][8][128];
    const float* W    = blockIdx.z ? W1 : W0;
    const float* bias = blockIdx.z ? b1 : b0;
    float*       C    = blockIdx.z ? C1 : C0;

    int tid = threadIdx.x;
    int m0 = blockIdx.y * 128, n0 = blockIdx.x * 128;
    int ar = tid >> 1, ak = (tid & 1) * 4;
    const float* Arow = A + (size_t)(m0 + ar) * Kdim + ak;
    const float* Brow = W + (size_t)(n0 + ar) * Kdim + ak;
    int tx = tid & 15, ty = tid >> 4;
    float acc[8][8];
#pragma unroll
    for (int i = 0; i < 8; i++)
#pragma unroll
        for (int j = 0; j < 8; j++) acc[i][j] = 0.f;

    float4 av = *(const float4*)(Arow);
    float4 bv = *(const float4*)(Brow);
    int buf = 0;
    for (int k0 = 0; k0 < Kdim; k0 += 8) {
        As[buf][ak + 0][ar] = av.x; As[buf][ak + 1][ar] = av.y;
        As[buf][ak + 2][ar] = av.z; As[buf][ak + 3][ar] = av.w;
        Bs[buf][ak + 0][ar] = bv.x; Bs[buf][ak + 1][ar] = bv.y;
        Bs[buf][ak + 2][ar] = bv.z; Bs[buf][ak + 3][ar] = bv.w;
        __syncthreads();
        if (k0 + 8 < Kdim) {
            av = *(const float4*)(Arow + k0 + 8);
            bv = *(const float4*)(Brow + k0 + 8);
        }
#pragma unroll
        for (int kk = 0; kk < 8; kk++) {
            float a[8], b[8];
            *(float4*)(a)     = *(const float4*)&As[buf][kk][ty * 8];
            *(float4*)(a + 4) = *(const float4*)&As[buf][kk][ty * 8 + 4];
            *(float4*)(b)     = *(const float4*)&Bs[buf][kk][tx * 8];
            *(float4*)(b + 4) = *(const float4*)&Bs[buf][kk][tx * 8 + 4];
#pragma unroll
            for (int i = 0; i < 8; i++)
#pragma unroll
                for (int j = 0; j < 8; j++) acc[i][j] = fmaf(a[i], b[j], acc[i][j]);
        }
        buf ^= 1;
    }
#pragma unroll
    for (int i = 0; i < 8; i++) {
        float* orow = C + (size_t)(m0 + ty * 8 + i) * ldc;
#pragma unroll
        for (int j = 0; j < 8; j++) {
            int nn = n0 + tx * 8 + j;
            orow[nn] = acc[i][j] + bias[nn];
        }
    }
}

// ---- persistent bidirectional LSTM: 128 blocks x 128 threads ----
__global__ __launch_bounds__(128) void k_lstm(const float* __restrict__ Whf,
                                              const float* __restrict__ Whb) {
    __shared__ float4 w4[16][65];   // 16 gate rows x 256 k
    __shared__ float4 h4[32][33];   // 32 batches x 128 k (half)
    __shared__ float  z_s[16 * 33];

    int tid = threadIdx.x, bi = blockIdx.x;
    int dir = bi >> 6, u0 = (bi & 63) * 4;
    const float* Whh = dir ? Whb : Whf;

    for (int i = tid; i < 16 * 64; i += 128) {
        int gl = i >> 6, kq = i & 63;
        int q = gl >> 2, ul = gl & 3;
        w4[gl][kq] = *(const float4*)(Whh + (size_t)(q * 256 + u0 + ul) * 256 + kq * 4);
    }
    __syncthreads();

    int gp = tid >> 4, bp = tid & 15;
    int gA = gp * 2, gB = gA + 1, bB = bp + 16;
    int a_ul = tid & 3, a_b = tid >> 2;
    const float* xz = g_xz + (size_t)dir * XZS;
    float c_reg = 0.f;

    for (int s = 0; s < T_LEN; s++) {
        int t = dir ? (T_LEN - 1 - s) : s;
        const float* xzp = xz + (size_t)(a_b * T_LEN + t) * G4 + u0 + a_ul;
        float xzi = xzp[0], xzf = xzp[256], xzg = xzp[512], xzo = xzp[768];

        float a00 = 0.f, a01 = 0.f, a10 = 0.f, a11 = 0.f;
        if (s > 0) {
            int tp = dir ? (T_LEN - s) : (s - 1);
#pragma unroll
            for (int p = 0; p < 2; p++) {
                __syncthreads();
                for (int i = tid; i < 32 * 32; i += 128) {
                    int b = i >> 5, kq = i & 31;
                    h4[b][kq] = *(const float4*)(g_h + (size_t)(b * T_LEN + tp) * D_L +
                                                 dir * 256 + p * 128 + kq * 4);
                }
                __syncthreads();
#pragma unroll 8
                for (int kq = 0; kq < 32; kq++) {
                    float4 w0 = w4[gA][p * 32 + kq], w1 = w4[gB][p * 32 + kq];
                    float4 hA = h4[bp][kq], hB = h4[bB][kq];
                    a00 = fmaf(w0.x, hA.x, fmaf(w0.y, hA.y, fmaf(w0.z, hA.z, fmaf(w0.w, hA.w, a00))));
                    a01 = fmaf(w0.x, hB.x, fmaf(w0.y, hB.y, fmaf(w0.z, hB.z, fmaf(w0.w, hB.w, a01))));
                    a10 = fmaf(w1.x, hA.x, fmaf(w1.y, hA.y, fmaf(w1.z, hA.z, fmaf(w1.w, hA.w, a10))));
                    a11 = fmaf(w1.x, hB.x, fmaf(w1.y, hB.y, fmaf(w1.z, hB.z, fmaf(w1.w, hB.w, a11))));
                }
            }
        }
        z_s[gA * 33 + bp] = a00; z_s[gA * 33 + bB] = a01;
        z_s[gB * 33 + bp] = a10; z_s[gB * 33 + bB] = a11;
        __syncthreads();

        float zi = z_s[(0 + a_ul) * 33 + a_b] + xzi;
        float zf = z_s[(4 + a_ul) * 33 + a_b] + xzf;
        float zg = z_s[(8 + a_ul) * 33 + a_b] + xzg;
        float zo = z_s[(12 + a_ul) * 33 + a_b] + xzo;
        c_reg = fmaf(sigf(zf), c_reg, sigf(zi) * tanhf(zg));
        g_h[(size_t)(a_b * T_LEN + t) * D_L + dir * 256 + u0 + a_ul] = sigf(zo) * tanhf(c_reg);
        grid_sync();
    }
}

// ---- sq/sk projections + copy h into concat buffer ----
__global__ __launch_bounds__(256) void k_sqsk(const float* __restrict__ W1) {
    __shared__ float W1s[10 * 1024];
    int tid = threadIdx.x;
    for (int i = tid; i < 2560; i += 256) ((float4*)W1s)[i] = ((const float4*)W1)[i];
    __syncthreads();
    int w = tid >> 5, l = tid & 31;
    int row = blockIdx.x * 8 + w;
    const float4* hrow = (const float4*)(g_h + (size_t)row * D_L);
    float4* hcr = (float4*)(g_hc + (size_t)row * 1024);
    float4 hr[4];
#pragma unroll
    for (int j = 0; j < 4; j++) { hr[j] = hrow[l + 32 * j]; hcr[l + 32 * j] = hr[j]; }
#pragma unroll
    for (int xx = 0; xx < 10; xx++) {
        float sq = 0.f, sk = 0.f;
#pragma unroll
        for (int j = 0; j < 4; j++) {
            const float* wq = &W1s[xx * 1024 + (l + 32 * j) * 4];
            sq = fmaf(hr[j].x, wq[0], fmaf(hr[j].y, wq[1], fmaf(hr[j].z, wq[2], fmaf(hr[j].w, wq[3], sq))));
            sk = fmaf(hr[j].x, wq[512], fmaf(hr[j].y, wq[513], fmaf(hr[j].z, wq[514], fmaf(hr[j].w, wq[515], sk))));
        }
#pragma unroll
        for (int o = 16; o > 0; o >>= 1) {
            sq += __shfl_xor_sync(0xffffffffu, sq, o);
            sk += __shfl_xor_sync(0xffffffffu, sk, o);
        }
        if (l == 0) { g_sq[row * 10 + xx] = sq; g_sk[row * 10 + xx] = sk; }
    }
}

// ---- fused attention: scores -> softmax -> context ----
__global__ __launch_bounds__(256) void k_attn(const float* __restrict__ mask,
                                              const float* __restrict__ W2) {
    __shared__ float sc[32 * 257];
    __shared__ float sk_s[2560], sq_s[320], w2s[16], madd[256];
    int b = blockIdx.y, q0 = blockIdx.x * 32, tid = threadIdx.x;
    int row0 = b * T_LEN;

    for (int i = tid; i < 2560; i += 256) sk_s[i] = g_sk[row0 * 10 + i];
    for (int i = tid; i < 320; i += 256)  sq_s[i] = g_sq[(row0 + q0) * 10 + i];
    if (tid < 10) w2s[tid] = W2[tid];
    madd[tid] = (mask[row0 + tid] == 0.0f) ? -1e30f : 0.0f;
    __syncthreads();

    {
        float skr[10];
#pragma unroll
        for (int xx = 0; xx < 10; xx++) skr[xx] = sk_s[tid * 10 + xx];
        float mk = madd[tid];
        for (int q = 0; q < 32; q++) {
            float a = 0.f;
#pragma unroll
            for (int xx = 0; xx < 10; xx++)
                a = fmaf(w2s[xx], tanhf(sq_s[q * 10 + xx] + skr[xx]), a);
            sc[q * 257 + tid] = a + mk;
        }
    }
    __syncthreads();

    {
        int w = tid >> 5, l = tid & 31;
        for (int q = w; q < 32; q += 8) {
            float v[8], mx = -1e30f;
#pragma unroll
            for (int j = 0; j < 8; j++) { v[j] = sc[q * 257 + l + 32 * j]; mx = fmaxf(mx, v[j]); }
#pragma unroll
            for (int o = 16; o > 0; o >>= 1) mx = fmaxf(mx, __shfl_xor_sync(0xffffffffu, mx, o));
            float sum = 0.f;
#pragma unroll
            for (int j = 0; j < 8; j++) { v[j] = __expf(v[j] - mx); sum += v[j]; }
#pragma unroll
            for (int o = 16; o > 0; o >>= 1) sum += __shfl_xor_sync(0xffffffffu, sum, o);
            float inv = 1.0f / sum;
#pragma unroll
            for (int j = 0; j < 8; j++) sc[q * 257 + l + 32 * j] = v[j] * inv;
        }
    }
    __syncthreads();

    int qg = tid & 7, dq = tid >> 3;
    float4 acc[4][4];
#pragma unroll
    for (int j = 0; j < 4; j++)
#pragma unroll
        for (int c = 0; c < 4; c++) acc[j][c] = make_float4(0.f, 0.f, 0.f, 0.f);

    for (int k = 0; k < 256; k++) {
        const float4* hrow = (const float4*)(g_h + (size_t)(row0 + k) * D_L) + dq * 4;
        float4 hv[4];
#pragma unroll
        for (int c = 0; c < 4; c++) hv[c] = hrow[c];
#pragma unroll
        for (int j = 0; j < 4; j++) {
            float wq = sc[(qg * 4 + j) * 257 + k];
#pragma unroll
            for (int c = 0; c < 4; c++) {
                acc[j][c].x = fmaf(wq, hv[c].x, acc[j][c].x);
                acc[j][c].y = fmaf(wq, hv[c].y, acc[j][c].y);
                acc[j][c].z = fmaf(wq, hv[c].z, acc[j][c].z);
                acc[j][c].w = fmaf(wq, hv[c].w, acc[j][c].w);
            }
        }
    }
#pragma unroll
    for (int j = 0; j < 4; j++) {
        float4* orow = (float4*)(g_hc + (size_t)(row0 + q0 + qg * 4 + j) * 1024 + 512) + dq * 4;
#pragma unroll
        for (int c = 0; c < 4; c++) orow[c] = acc[j][c];
    }
}

extern "C" void kernel_launch(void* const* d_in, const int* in_sizes, int n_in,
                              void* d_out, int out_size) {
    const float* x     = (const float*)d_in[0];
    const float* mask  = (const float*)d_in[1];
    const float* Wih_f = (const float*)d_in[2];
    const float* Whh_f = (const float*)d_in[3];
    const float* b_f   = (const float*)d_in[4];
    const float* Wih_b = (const float*)d_in[5];
    const float* Whh_b = (const float*)d_in[6];
    const float* b_b   = (const float*)d_in[7];
    const float* W1    = (const float*)d_in[8];
    const float* W2    = (const float*)d_in[9];
    const float* W3    = (const float*)d_in[10];
    const float* b3    = (const float*)d_in[11];

    float* xzf;  cudaGetSymbolAddress((void**)&xzf, g_xz);
    float* xzb = xzf + XZS;
    float* hc;   cudaGetSymbolAddress((void**)&hc, g_hc);
    float* out = (float*)d_out;

    // both direction projections in one launch (z picks weights)
    k_gemm<<<dim3(8, 64, 2), 256>>>(x, D_IN, Wih_f, b_f, xzf, Wih_b, b_b, xzb, G4);
    k_lstm<<<128, 128>>>(Whh_f, Whh_b);
    k_sqsk<<<1024, 256>>>(W1);
    k_attn<<<dim3(8, 32), 256>>>(mask, W2);
    k_gemm<<<dim3(4, 64, 1), 256>>>(hc, 1024, W3, b3, out, W3, b3, out, D_L);
}

// round 6
// speedup vs baseline: 1.2518x; 1.1686x over previous
#include <cuda_runtime.h>
#include <math.h>
#include <stdint.h>

#define T_LEN 256
#define G4    1024
#define D_IN  768
#define D_L   512
#define NROWS 8192
#define XZS   (NROWS * G4)

__device__ float g_xz[2 * XZS];
__device__ float g_h [NROWS * D_L];
__device__ float g_hc[NROWS * 1024];
__device__ float g_sq[NROWS * 10];
__device__ float g_sk[NROWS * 10];
__device__ unsigned g_bar_count, g_bar_gen;

__device__ __forceinline__ unsigned ld_acq(unsigned* p) {
    unsigned v;
    asm volatile("ld.acquire.gpu.u32 %0, [%1];" : "=r"(v) : "l"(p) : "memory");
    return v;
}
__device__ __forceinline__ void grid_sync() {
    __syncthreads();
    if (threadIdx.x == 0) {
        unsigned gen = ld_acq(&g_bar_gen);
        __threadfence();
        if (atomicAdd(&g_bar_count, 1u) == 127u) {
            g_bar_count = 0u; __threadfence(); atomicAdd(&g_bar_gen, 1u);
        } else { while (ld_acq(&g_bar_gen) == gen) { } }
        __threadfence();
    }
    __syncthreads();
}
__device__ __forceinline__ float sigf(float x) { return fmaf(0.5f, tanhf(0.5f * x), 0.5f); }
__device__ __forceinline__ float htanh(float x) {
    float r; asm("tanh.approx.f32 %0, %1;" : "=f"(r) : "f"(x)); return r;
}
__device__ __forceinline__ uint32_t f2tf(float x) {
    uint32_t r; asm("cvt.rna.tf32.f32 %0, %1;" : "=r"(r) : "f"(x)); return r;
}

// ---- tf32 tensor-core GEMM: C[m][n] = A[m][:] . W[n][:] + bias[n] ----
__global__ __launch_bounds__(256) void k_gemm(const float* __restrict__ A, int Kdim,
                                              const float* __restrict__ W0,
                                              const float* __restrict__ b0,
                                              float* __restrict__ C0,
                                              const float* __restrict__ W1,
                                              const float* __restrict__ b1,
                                              float* __restrict__ C1, int ldc) {
    __shared__ uint32_t As[2][8][136], Bs[2][8][136];
    const float* W    = blockIdx.z ? W1 : W0;
    const float* bias = blockIdx.z ? b1 : b0;
    float*       C    = blockIdx.z ? C1 : C0;

    int tid = threadIdx.x, lane = tid & 31, wid = tid >> 5;
    int m0 = blockIdx.y * 128, n0 = blockIdx.x * 128;
    int mb = (wid >> 2) * 64, nb = (wid & 3) * 32;
    int ar = tid >> 1, ak = (tid & 1) * 4;
    const float* Arow = A + (size_t)(m0 + ar) * Kdim + ak;
    const float* Brow = W + (size_t)(n0 + ar) * Kdim + ak;

    float acc[4][4][4];
#pragma unroll
    for (int i = 0; i < 4; i++)
#pragma unroll
        for (int j = 0; j < 4; j++)
#pragma unroll
            for (int c = 0; c < 4; c++) acc[i][j][c] = 0.f;

    int kq = lane & 3, gq = lane >> 2;
    float4 av = *(const float4*)(Arow);
    float4 bv = *(const float4*)(Brow);
    int buf = 0;
    for (int k0 = 0; k0 < Kdim; k0 += 8) {
        As[buf][ak + 0][ar] = f2tf(av.x); As[buf][ak + 1][ar] = f2tf(av.y);
        As[buf][ak + 2][ar] = f2tf(av.z); As[buf][ak + 3][ar] = f2tf(av.w);
        Bs[buf][ak + 0][ar] = f2tf(bv.x); Bs[buf][ak + 1][ar] = f2tf(bv.y);
        Bs[buf][ak + 2][ar] = f2tf(bv.z); Bs[buf][ak + 3][ar] = f2tf(bv.w);
        __syncthreads();
        if (k0 + 8 < Kdim) {
            av = *(const float4*)(Arow + k0 + 8);
            bv = *(const float4*)(Brow + k0 + 8);
        }
        uint32_t a[4][4], b[4][2];
#pragma unroll
        for (int mf = 0; mf < 4; mf++) {
            int r = mb + mf * 16 + gq;
            a[mf][0] = As[buf][kq][r];     a[mf][1] = As[buf][kq][r + 8];
            a[mf][2] = As[buf][kq + 4][r]; a[mf][3] = As[buf][kq + 4][r + 8];
        }
#pragma unroll
        for (int nf = 0; nf < 4; nf++) {
            int c = nb + nf * 8 + gq;
            b[nf][0] = Bs[buf][kq][c]; b[nf][1] = Bs[buf][kq + 4][c];
        }
#pragma unroll
        for (int mf = 0; mf < 4; mf++)
#pragma unroll
            for (int nf = 0; nf < 4; nf++)
                asm volatile(
                    "mma.sync.aligned.m16n8k8.row.col.f32.tf32.tf32.f32 "
                    "{%0,%1,%2,%3}, {%4,%5,%6,%7}, {%8,%9}, {%0,%1,%2,%3};"
                    : "+f"(acc[mf][nf][0]), "+f"(acc[mf][nf][1]),
                      "+f"(acc[mf][nf][2]), "+f"(acc[mf][nf][3])
                    : "r"(a[mf][0]), "r"(a[mf][1]), "r"(a[mf][2]), "r"(a[mf][3]),
                      "r"(b[nf][0]), "r"(b[nf][1]));
        buf ^= 1;
        __syncthreads();
    }
#pragma unroll
    for (int mf = 0; mf < 4; mf++)
#pragma unroll
        for (int nf = 0; nf < 4; nf++) {
            int row = m0 + mb + mf * 16 + gq;
            int col = n0 + nb + nf * 8 + 2 * kq;
            float b0v = bias[col], b1v = bias[col + 1];
            float* p0 = C + (size_t)row * ldc + col;
            float* p1 = C + (size_t)(row + 8) * ldc + col;
            p0[0] = acc[mf][nf][0] + b0v; p0[1] = acc[mf][nf][1] + b1v;
            p1[0] = acc[mf][nf][2] + b0v; p1[1] = acc[mf][nf][3] + b1v;
        }
}

// ---- persistent bidirectional LSTM ----
__global__ __launch_bounds__(128) void k_lstm(const float* __restrict__ Whf,
                                              const float* __restrict__ Whb) {
    __shared__ float4 w4[16][65];
    __shared__ float4 h4[32][33];
    __shared__ float  z_s[16 * 33];
    int tid = threadIdx.x, bi = blockIdx.x;
    int dir = bi >> 6, u0 = (bi & 63) * 4;
    const float* Whh = dir ? Whb : Whf;
    for (int i = tid; i < 16 * 64; i += 128) {
        int gl = i >> 6, kq = i & 63;
        int q = gl >> 2, ul = gl & 3;
        w4[gl][kq] = *(const float4*)(Whh + (size_t)(q * 256 + u0 + ul) * 256 + kq * 4);
    }
    __syncthreads();
    int gp = tid >> 4, bp = tid & 15;
    int gA = gp * 2, gB = gA + 1, bB = bp + 16;
    int a_ul = tid & 3, a_b = tid >> 2;
    const float* xz = g_xz + (size_t)dir * XZS;
    float c_reg = 0.f;
    for (int s = 0; s < T_LEN; s++) {
        int t = dir ? (T_LEN - 1 - s) : s;
        const float* xzp = xz + (size_t)(a_b * T_LEN + t) * G4 + u0 + a_ul;
        float xzi = xzp[0], xzf = xzp[256], xzg = xzp[512], xzo = xzp[768];
        float a00 = 0.f, a01 = 0.f, a10 = 0.f, a11 = 0.f;
        if (s > 0) {
            int tp = dir ? (T_LEN - s) : (s - 1);
#pragma unroll
            for (int p = 0; p < 2; p++) {
                __syncthreads();
                for (int i = tid; i < 32 * 32; i += 128) {
                    int b = i >> 5, kq = i & 31;
                    h4[b][kq] = *(const float4*)(g_h + (size_t)(b * T_LEN + tp) * D_L +
                                                 dir * 256 + p * 128 + kq * 4);
                }
                __syncthreads();
#pragma unroll 8
                for (int kq = 0; kq < 32; kq++) {
                    float4 w0 = w4[gA][p * 32 + kq], w1 = w4[gB][p * 32 + kq];
                    float4 hA = h4[bp][kq], hB = h4[bB][kq];
                    a00 = fmaf(w0.x, hA.x, fmaf(w0.y, hA.y, fmaf(w0.z, hA.z, fmaf(w0.w, hA.w, a00))));
                    a01 = fmaf(w0.x, hB.x, fmaf(w0.y, hB.y, fmaf(w0.z, hB.z, fmaf(w0.w, hB.w, a01))));
                    a10 = fmaf(w1.x, hA.x, fmaf(w1.y, hA.y, fmaf(w1.z, hA.z, fmaf(w1.w, hA.w, a10))));
                    a11 = fmaf(w1.x, hB.x, fmaf(w1.y, hB.y, fmaf(w1.z, hB.z, fmaf(w1.w, hB.w, a11))));
                }
            }
        }
        z_s[gA * 33 + bp] = a00; z_s[gA * 33 + bB] = a01;
        z_s[gB * 33 + bp] = a10; z_s[gB * 33 + bB] = a11;
        __syncthreads();
        float zi = z_s[(0 + a_ul) * 33 + a_b] + xzi;
        float zf = z_s[(4 + a_ul) * 33 + a_b] + xzf;
        float zg = z_s[(8 + a_ul) * 33 + a_b] + xzg;
        float zo = z_s[(12 + a_ul) * 33 + a_b] + xzo;
        c_reg = fmaf(sigf(zf), c_reg, sigf(zi) * tanhf(zg));
        g_h[(size_t)(a_b * T_LEN + t) * D_L + dir * 256 + u0 + a_ul] = sigf(zo) * tanhf(c_reg);
        grid_sync();
    }
}

// ---- sq/sk projections + copy h into concat buffer ----
__global__ __launch_bounds__(256) void k_sqsk(const float* __restrict__ W1) {
    __shared__ float W1s[10 * 1024];
    int tid = threadIdx.x;
    for (int i = tid; i < 2560; i += 256) ((float4*)W1s)[i] = ((const float4*)W1)[i];
    __syncthreads();
    int w = tid >> 5, l = tid & 31;
    int row = blockIdx.x * 8 + w;
    const float4* hrow = (const float4*)(g_h + (size_t)row * D_L);
    float4* hcr = (float4*)(g_hc + (size_t)row * 1024);
    float4 hr[4];
#pragma unroll
    for (int j = 0; j < 4; j++) { hr[j] = hrow[l + 32 * j]; hcr[l + 32 * j] = hr[j]; }
#pragma unroll
    for (int xx = 0; xx < 10; xx++) {
        float sq = 0.f, sk = 0.f;
#pragma unroll
        for (int j = 0; j < 4; j++) {
            const float* wq = &W1s[xx * 1024 + (l + 32 * j) * 4];
            sq = fmaf(hr[j].x, wq[0], fmaf(hr[j].y, wq[1], fmaf(hr[j].z, wq[2], fmaf(hr[j].w, wq[3], sq))));
            sk = fmaf(hr[j].x, wq[512], fmaf(hr[j].y, wq[513], fmaf(hr[j].z, wq[514], fmaf(hr[j].w, wq[515], sk))));
        }
#pragma unroll
        for (int o = 16; o > 0; o >>= 1) {
            sq += __shfl_xor_sync(0xffffffffu, sq, o);
            sk += __shfl_xor_sync(0xffffffffu, sk, o);
        }
        if (l == 0) { g_sq[row * 10 + xx] = sq; g_sk[row * 10 + xx] = sk; }
    }
}

// ---- fused attention, 16-q tiles, HW tanh ----
__global__ __launch_bounds__(256) void k_attn(const float* __restrict__ mask,
                                              const float* __restrict__ W2) {
    __shared__ float sc[16 * 257];
    __shared__ float sk_s[2560], sq_s[160], w2s[16], madd[256];
    int b = blockIdx.y, q0 = blockIdx.x * 16, tid = threadIdx.x;
    int row0 = b * T_LEN;
    for (int i = tid; i < 2560; i += 256) sk_s[i] = g_sk[row0 * 10 + i];
    if (tid < 160) sq_s[tid] = g_sq[(row0 + q0) * 10 + tid];
    if (tid < 10) w2s[tid] = W2[tid];
    madd[tid] = (mask[row0 + tid] == 0.0f) ? -1e30f : 0.0f;
    __syncthreads();
    {
        float skr[10];
#pragma unroll
        for (int xx = 0; xx < 10; xx++) skr[xx] = sk_s[tid * 10 + xx];
        float mk = madd[tid];
#pragma unroll 4
        for (int q = 0; q < 16; q++) {
            float a = 0.f;
#pragma unroll
            for (int xx = 0; xx < 10; xx++)
                a = fmaf(w2s[xx], htanh(sq_s[q * 10 + xx] + skr[xx]), a);
            sc[q * 257 + tid] = a + mk;
        }
    }
    __syncthreads();
    {
        int w = tid >> 5, l = tid & 31;
        for (int q = w; q < 16; q += 8) {
            float v[8], mx = -1e30f;
#pragma unroll
            for (int j = 0; j < 8; j++) { v[j] = sc[q * 257 + l + 32 * j]; mx = fmaxf(mx, v[j]); }
#pragma unroll
            for (int o = 16; o > 0; o >>= 1) mx = fmaxf(mx, __shfl_xor_sync(0xffffffffu, mx, o));
            float sum = 0.f;
#pragma unroll
            for (int j = 0; j < 8; j++) { v[j] = __expf(v[j] - mx); sum += v[j]; }
#pragma unroll
            for (int o = 16; o > 0; o >>= 1) sum += __shfl_xor_sync(0xffffffffu, sum, o);
            float inv = 1.0f / sum;
#pragma unroll
            for (int j = 0; j < 8; j++) sc[q * 257 + l + 32 * j] = v[j] * inv;
        }
    }
    __syncthreads();
    int qg = tid & 3, dq = tid >> 2;
    float4 acc[4][2];
#pragma unroll
    for (int j = 0; j < 4; j++) { acc[j][0] = make_float4(0,0,0,0); acc[j][1] = make_float4(0,0,0,0); }
    for (int k = 0; k < 256; k++) {
        const float4* hrow = (const float4*)(g_h + (size_t)(row0 + k) * D_L) + dq * 2;
        float4 h0 = hrow[0], h1 = hrow[1];
#pragma unroll
        for (int j = 0; j < 4; j++) {
            float wq = sc[(qg * 4 + j) * 257 + k];
            acc[j][0].x = fmaf(wq, h0.x, acc[j][0].x); acc[j][0].y = fmaf(wq, h0.y, acc[j][0].y);
            acc[j][0].z = fmaf(wq, h0.z, acc[j][0].z); acc[j][0].w = fmaf(wq, h0.w, acc[j][0].w);
            acc[j][1].x = fmaf(wq, h1.x, acc[j][1].x); acc[j][1].y = fmaf(wq, h1.y, acc[j][1].y);
            acc[j][1].z = fmaf(wq, h1.z, acc[j][1].z); acc[j][1].w = fmaf(wq, h1.w, acc[j][1].w);
        }
    }
#pragma unroll
    for (int j = 0; j < 4; j++) {
        float4* orow = (float4*)(g_hc + (size_t)(row0 + q0 + qg * 4 + j) * 1024 + 512) + dq * 2;
        orow[0] = acc[j][0]; orow[1] = acc[j][1];
    }
}

extern "C" void kernel_launch(void* const* d_in, const int* in_sizes, int n_in,
                              void* d_out, int out_size) {
    const float* x     = (const float*)d_in[0];
    const float* mask  = (const float*)d_in[1];
    const float* Wih_f = (const float*)d_in[2];
    const float* Whh_f = (const float*)d_in[3];
    const float* b_f   = (const float*)d_in[4];
    const float* Wih_b = (const float*)d_in[5];
    const float* Whh_b = (const float*)d_in[6];
    const float* b_b   = (const float*)d_in[7];
    const float* W1    = (const float*)d_in[8];
    const float* W2    = (const float*)d_in[9];
    const float* W3    = (const float*)d_in[10];
    const float* b3    = (const float*)d_in[11];

    float* xzf;  cudaGetSymbolAddress((void**)&xzf, g_xz);
    float* xzb = xzf + XZS;
    float* hc;   cudaGetSymbolAddress((void**)&hc, g_hc);
    float* out = (float*)d_out;

    k_gemm<<<dim3(8, 64, 2), 256>>>(x, D_IN, Wih_f, b_f, xzf, Wih_b, b_b, xzb, G4);
    k_lstm<<<128, 128>>>(Whh_f, Whh_b);
    k_sqsk<<<1024, 256>>>(W1);
    k_attn<<<dim3(16, 32), 256>>>(mask, W2);
    k_gemm<<<dim3(4, 64, 1), 256>>>(hc, 1024, W3, b3, out, W3, b3, out, D_L);
}

// round 7
// speedup vs baseline: 1.7044x; 1.3615x over previous
#include <cuda_runtime.h>
#include <math.h>
#include <stdint.h>

#define T_LEN 256
#define G4    1024
#define D_IN  768
#define D_L   512
#define NROWS 8192
#define XZS   (NROWS * G4)
typedef unsigned long long ull;

__device__ float g_xz[2 * XZS];
__device__ float g_h [NROWS * D_L];
__device__ float g_hc[NROWS * 1024];
__device__ float g_sq[NROWS * 10];
__device__ float g_sk[NROWS * 10];
__device__ unsigned g_cnt[2];
__device__ unsigned g_flag[2 * 64 * 8];   // 32B-spaced per-block release flags

__device__ __forceinline__ unsigned ld_acq(const unsigned* p) {
    unsigned v;
    asm volatile("ld.acquire.gpu.global.u32 %0, [%1];" : "=r"(v) : "l"(p) : "memory");
    return v;
}
__device__ __forceinline__ void st_rel(unsigned* p, unsigned v) {
    asm volatile("st.release.gpu.global.u32 [%0], %1;" :: "l"(p), "r"(v) : "memory");
}
__device__ __forceinline__ void fma2(ull& d, ull a, ull b) {
    asm("fma.rn.f32x2 %0, %1, %2, %0;" : "+l"(d) : "l"(a), "l"(b));
}
__device__ __forceinline__ float hsum2(ull v) {
    float lo, hi; asm("mov.b64 {%0,%1}, %2;" : "=f"(lo), "=f"(hi) : "l"(v));
    return lo + hi;
}
__device__ __forceinline__ float fsig(float x) {
    return __fdividef(1.0f, 1.0f + __expf(-x));
}
__device__ __forceinline__ float ftanh(float x) {
    return fmaf(2.0f, fsig(2.0f * x), -1.0f);
}
__device__ __forceinline__ float htanh(float x) {
    float r; asm("tanh.approx.f32 %0, %1;" : "=f"(r) : "f"(x)); return r;
}
__device__ __forceinline__ uint32_t f2tf(float x) {
    uint32_t r; asm("cvt.rna.tf32.f32 %0, %1;" : "=r"(r) : "f"(x)); return r;
}

// ---- tf32 tensor-core GEMM (unchanged from R6) ----
__global__ __launch_bounds__(256) void k_gemm(const float* __restrict__ A, int Kdim,
                                              const float* __restrict__ W0,
                                              const float* __restrict__ b0,
                                              float* __restrict__ C0,
                                              const float* __restrict__ W1,
                                              const float* __restrict__ b1,
                                              float* __restrict__ C1, int ldc) {
    __shared__ uint32_t As[2][8][136], Bs[2][8][136];
    const float* W    = blockIdx.z ? W1 : W0;
    const float* bias = blockIdx.z ? b1 : b0;
    float*       C    = blockIdx.z ? C1 : C0;
    int tid = threadIdx.x, lane = tid & 31, wid = tid >> 5;
    int m0 = blockIdx.y * 128, n0 = blockIdx.x * 128;
    int mb = (wid >> 2) * 64, nb = (wid & 3) * 32;
    int ar = tid >> 1, ak = (tid & 1) * 4;
    const float* Arow = A + (size_t)(m0 + ar) * Kdim + ak;
    const float* Brow = W + (size_t)(n0 + ar) * Kdim + ak;
    float acc[4][4][4];
#pragma unroll
    for (int i = 0; i < 4; i++)
#pragma unroll
        for (int j = 0; j < 4; j++)
#pragma unroll
            for (int c = 0; c < 4; c++) acc[i][j][c] = 0.f;
    int kq = lane & 3, gq = lane >> 2;
    float4 av = *(const float4*)(Arow);
    float4 bv = *(const float4*)(Brow);
    int buf = 0;
    for (int k0 = 0; k0 < Kdim; k0 += 8) {
        As[buf][ak + 0][ar] = f2tf(av.x); As[buf][ak + 1][ar] = f2tf(av.y);
        As[buf][ak + 2][ar] = f2tf(av.z); As[buf][ak + 3][ar] = f2tf(av.w);
        Bs[buf][ak + 0][ar] = f2tf(bv.x); Bs[buf][ak + 1][ar] = f2tf(bv.y);
        Bs[buf][ak + 2][ar] = f2tf(bv.z); Bs[buf][ak + 3][ar] = f2tf(bv.w);
        __syncthreads();
        if (k0 + 8 < Kdim) {
            av = *(const float4*)(Arow + k0 + 8);
            bv = *(const float4*)(Brow + k0 + 8);
        }
        uint32_t a[4][4], b[4][2];
#pragma unroll
        for (int mf = 0; mf < 4; mf++) {
            int r = mb + mf * 16 + gq;
            a[mf][0] = As[buf][kq][r];     a[mf][1] = As[buf][kq][r + 8];
            a[mf][2] = As[buf][kq + 4][r]; a[mf][3] = As[buf][kq + 4][r + 8];
        }
#pragma unroll
        for (int nf = 0; nf < 4; nf++) {
            int c = nb + nf * 8 + gq;
            b[nf][0] = Bs[buf][kq][c]; b[nf][1] = Bs[buf][kq + 4][c];
        }
#pragma unroll
        for (int mf = 0; mf < 4; mf++)
#pragma unroll
            for (int nf = 0; nf < 4; nf++)
                asm volatile(
                    "mma.sync.aligned.m16n8k8.row.col.f32.tf32.tf32.f32 "
                    "{%0,%1,%2,%3}, {%4,%5,%6,%7}, {%8,%9}, {%0,%1,%2,%3};"
                    : "+f"(acc[mf][nf][0]), "+f"(acc[mf][nf][1]),
                      "+f"(acc[mf][nf][2]), "+f"(acc[mf][nf][3])
                    : "r"(a[mf][0]), "r"(a[mf][1]), "r"(a[mf][2]), "r"(a[mf][3]),
                      "r"(b[nf][0]), "r"(b[nf][1]));
        buf ^= 1;
        __syncthreads();
    }
#pragma unroll
    for (int mf = 0; mf < 4; mf++)
#pragma unroll
        for (int nf = 0; nf < 4; nf++) {
            int row = m0 + mb + mf * 16 + gq;
            int col = n0 + nb + nf * 8 + 2 * kq;
            float b0v = bias[col], b1v = bias[col + 1];
            float* p0 = C + (size_t)row * ldc + col;
            float* p1 = C + (size_t)(row + 8) * ldc + col;
            p0[0] = acc[mf][nf][0] + b0v; p0[1] = acc[mf][nf][1] + b1v;
            p1[0] = acc[mf][nf][2] + b0v; p1[1] = acc[mf][nf][3] + b1v;
        }
}

// ---- persistent bidirectional LSTM: 128 blocks x 128 threads, f32x2 + flag barrier ----
__global__ __launch_bounds__(128) void k_lstm(const float* __restrict__ Whf,
                                              const float* __restrict__ Whb) {
    __shared__ float4 w4[16 * 64];              // 16KB, broadcast reads (no pad needed)
    __shared__ float4 h4[32 * 64];              // 32KB, XOR-swizzled; head aliased below
    float* z_s   = (float*)h4;                  // [16*33] floats, aliases h4[0..131]
    int*  s_last = (int*)(h4 + 132);            // aliases h4[132]

    int tid = threadIdx.x, bi = blockIdx.x;
    int dir = bi >> 6, blk = bi & 63, u0 = blk * 4;
    const float* Whh = dir ? Whb : Whf;
    unsigned fb = g_flag[(dir * 64 + (tid & 63)) * 8];   // common base (all slots equal)

    for (int i = tid; i < 16 * 64; i += 128) {
        int gl = i >> 6, kq = i & 63;
        int q = gl >> 2, ul = gl & 3;
        w4[gl * 64 + kq] = *(const float4*)(Whh + (size_t)(q * 256 + u0 + ul) * 256 + kq * 4);
    }
    __syncthreads();

    int gp = tid >> 4, bp = tid & 15;
    int gA = gp * 2, gB = gA + 1, bB = bp + 16;
    int a_ul = tid & 3, a_b = tid >> 2;
    const float* xz = g_xz + (size_t)dir * XZS;
    float c_reg = 0.f;

    for (int s = 0; s < T_LEN; s++) {
        int t = dir ? (T_LEN - 1 - s) : s;
        const float* xzp = xz + (size_t)(a_b * T_LEN + t) * G4 + u0 + a_ul;
        float xzi = xzp[0], xzf = xzp[256], xzg = xzp[512], xzo = xzp[768];

        float zi = xzi, zf = xzf, zg = xzg, zo = xzo;
        if (s > 0) {
            int tp = dir ? (T_LEN - s) : (s - 1);
            for (int i = tid; i < 32 * 64; i += 128) {      // 16 LDG.128 / thread
                int b = i >> 6, kq = i & 63;
                h4[b * 64 + (kq ^ (b & 7))] =
                    *(const float4*)(g_h + (size_t)(b * T_LEN + tp) * D_L + dir * 256 + kq * 4);
            }
            __syncthreads();
            ull a00 = 0, a01 = 0, a10 = 0, a11 = 0;
            int swA = bp & 7, swB = bB & 7;
#pragma unroll 4
            for (int kq = 0; kq < 64; kq++) {
                ulonglong2 w0 = *(const ulonglong2*)&w4[gA * 64 + kq];
                ulonglong2 w1 = *(const ulonglong2*)&w4[gB * 64 + kq];
                ulonglong2 hA = *(const ulonglong2*)&h4[bp * 64 + (kq ^ swA)];
                ulonglong2 hB = *(const ulonglong2*)&h4[bB * 64 + (kq ^ swB)];
                fma2(a00, w0.x, hA.x); fma2(a00, w0.y, hA.y);
                fma2(a01, w0.x, hB.x); fma2(a01, w0.y, hB.y);
                fma2(a10, w1.x, hA.x); fma2(a10, w1.y, hA.y);
                fma2(a11, w1.x, hB.x); fma2(a11, w1.y, hB.y);
            }
            __syncthreads();            // all h4 reads done before aliased z_s writes
            z_s[gA * 33 + bp] = hsum2(a00); z_s[gA * 33 + bB] = hsum2(a01);
            z_s[gB * 33 + bp] = hsum2(a10); z_s[gB * 33 + bB] = hsum2(a11);
            __syncthreads();
            zi += z_s[(0  + a_ul) * 33 + a_b];
            zf += z_s[(4  + a_ul) * 33 + a_b];
            zg += z_s[(8  + a_ul) * 33 + a_b];
            zo += z_s[(12 + a_ul) * 33 + a_b];
        }

        c_reg = fmaf(fsig(zf), c_reg, fsig(zi) * ftanh(zg));
        g_h[(size_t)(a_b * T_LEN + t) * D_L + dir * 256 + u0 + a_ul] = fsig(zo) * ftanh(c_reg);

        // ---- per-direction barrier with distributed release flags ----
        __syncthreads();
        if (tid == 0) {
            __threadfence();
            *s_last = (atomicAdd(&g_cnt[dir], 1u) == 63u) ? 1 : 0;
        }
        __syncthreads();
        if (*s_last) {
            if (tid == 0) { g_cnt[dir] = 0u; __threadfence(); }
            __syncthreads();
            if (tid < 64) st_rel(&g_flag[(dir * 64 + tid) * 8], fb + s + 1);
        } else {
            if (tid == 0) {
                while (ld_acq(&g_flag[(dir * 64 + blk) * 8]) < fb + s + 1) { }
                __threadfence();
            }
            __syncthreads();
        }
    }
}

// ---- sq/sk projections + copy h into concat buffer (unchanged) ----
__global__ __launch_bounds__(256) void k_sqsk(const float* __restrict__ W1) {
    __shared__ float W1s[10 * 1024];
    int tid = threadIdx.x;
    for (int i = tid; i < 2560; i += 256) ((float4*)W1s)[i] = ((const float4*)W1)[i];
    __syncthreads();
    int w = tid >> 5, l = tid & 31;
    int row = blockIdx.x * 8 + w;
    const float4* hrow = (const float4*)(g_h + (size_t)row * D_L);
    float4* hcr = (float4*)(g_hc + (size_t)row * 1024);
    float4 hr[4];
#pragma unroll
    for (int j = 0; j < 4; j++) { hr[j] = hrow[l + 32 * j]; hcr[l + 32 * j] = hr[j]; }
#pragma unroll
    for (int xx = 0; xx < 10; xx++) {
        float sq = 0.f, sk = 0.f;
#pragma unroll
        for (int j = 0; j < 4; j++) {
            const float* wq = &W1s[xx * 1024 + (l + 32 * j) * 4];
            sq = fmaf(hr[j].x, wq[0], fmaf(hr[j].y, wq[1], fmaf(hr[j].z, wq[2], fmaf(hr[j].w, wq[3], sq))));
            sk = fmaf(hr[j].x, wq[512], fmaf(hr[j].y, wq[513], fmaf(hr[j].z, wq[514], fmaf(hr[j].w, wq[515], sk))));
        }
#pragma unroll
        for (int o = 16; o > 0; o >>= 1) {
            sq += __shfl_xor_sync(0xffffffffu, sq, o);
            sk += __shfl_xor_sync(0xffffffffu, sk, o);
        }
        if (l == 0) { g_sq[row * 10 + xx] = sq; g_sk[row * 10 + xx] = sk; }
    }
}

// ---- fused attention (unchanged from R6) ----
__global__ __launch_bounds__(256) void k_attn(const float* __restrict__ mask,
                                              const float* __restrict__ W2) {
    __shared__ float sc[16 * 257];
    __shared__ float sk_s[2560], sq_s[160], w2s[16], madd[256];
    int b = blockIdx.y, q0 = blockIdx.x * 16, tid = threadIdx.x;
    int row0 = b * T_LEN;
    for (int i = tid; i < 2560; i += 256) sk_s[i] = g_sk[row0 * 10 + i];
    if (tid < 160) sq_s[tid] = g_sq[(row0 + q0) * 10 + tid];
    if (tid < 10) w2s[tid] = W2[tid];
    madd[tid] = (mask[row0 + tid] == 0.0f) ? -1e30f : 0.0f;
    __syncthreads();
    {
        float skr[10];
#pragma unroll
        for (int xx = 0; xx < 10; xx++) skr[xx] = sk_s[tid * 10 + xx];
        float mk = madd[tid];
#pragma unroll 4
        for (int q = 0; q < 16; q++) {
            float a = 0.f;
#pragma unroll
            for (int xx = 0; xx < 10; xx++)
                a = fmaf(w2s[xx], htanh(sq_s[q * 10 + xx] + skr[xx]), a);
            sc[q * 257 + tid] = a + mk;
        }
    }
    __syncthreads();
    {
        int w = tid >> 5, l = tid & 31;
        for (int q = w; q < 16; q += 8) {
            float v[8], mx = -1e30f;
#pragma unroll
            for (int j = 0; j < 8; j++) { v[j] = sc[q * 257 + l + 32 * j]; mx = fmaxf(mx, v[j]); }
#pragma unroll
            for (int o = 16; o > 0; o >>= 1) mx = fmaxf(mx, __shfl_xor_sync(0xffffffffu, mx, o));
            float sum = 0.f;
#pragma unroll
            for (int j = 0; j < 8; j++) { v[j] = __expf(v[j] - mx); sum += v[j]; }
#pragma unroll
            for (int o = 16; o > 0; o >>= 1) sum += __shfl_xor_sync(0xffffffffu, sum, o);
            float inv = 1.0f / sum;
#pragma unroll
            for (int j = 0; j < 8; j++) sc[q * 257 + l + 32 * j] = v[j] * inv;
        }
    }
    __syncthreads();
    int qg = tid & 3, dq = tid >> 2;
    float4 acc[4][2];
#pragma unroll
    for (int j = 0; j < 4; j++) { acc[j][0] = make_float4(0,0,0,0); acc[j][1] = make_float4(0,0,0,0); }
    for (int k = 0; k < 256; k++) {
        const float4* hrow = (const float4*)(g_h + (size_t)(row0 + k) * D_L) + dq * 2;
        float4 h0 = hrow[0], h1 = hrow[1];
#pragma unroll
        for (int j = 0; j < 4; j++) {
            float wq = sc[(qg * 4 + j) * 257 + k];
            acc[j][0].x = fmaf(wq, h0.x, acc[j][0].x); acc[j][0].y = fmaf(wq, h0.y, acc[j][0].y);
            acc[j][0].z = fmaf(wq, h0.z, acc[j][0].z); acc[j][0].w = fmaf(wq, h0.w, acc[j][0].w);
            acc[j][1].x = fmaf(wq, h1.x, acc[j][1].x); acc[j][1].y = fmaf(wq, h1.y, acc[j][1].y);
            acc[j][1].z = fmaf(wq, h1.z, acc[j][1].z); acc[j][1].w = fmaf(wq, h1.w, acc[j][1].w);
        }
    }
#pragma unroll
    for (int j = 0; j < 4; j++) {
        float4* orow = (float4*)(g_hc + (size_t)(row0 + q0 + qg * 4 + j) * 1024 + 512) + dq * 2;
        orow[0] = acc[j][0]; orow[1] = acc[j][1];
    }
}

extern "C" void kernel_launch(void* const* d_in, const int* in_sizes, int n_in,
                              void* d_out, int out_size) {
    const float* x     = (const float*)d_in[0];
    const float* mask  = (const float*)d_in[1];
    const float* Wih_f = (const float*)d_in[2];
    const float* Whh_f = (const float*)d_in[3];
    const float* b_f   = (const float*)d_in[4];
    const float* Wih_b = (const float*)d_in[5];
    const float* Whh_b = (const float*)d_in[6];
    const float* b_b   = (const float*)d_in[7];
    const float* W1    = (const float*)d_in[8];
    const float* W2    = (const float*)d_in[9];
    const float* W3    = (const float*)d_in[10];
    const float* b3    = (const float*)d_in[11];

    float* xzf;  cudaGetSymbolAddress((void**)&xzf, g_xz);
    float* xzb = xzf + XZS;
    float* hc;   cudaGetSymbolAddress((void**)&hc, g_hc);
    float* out = (float*)d_out;

    k_gemm<<<dim3(8, 64, 2), 256>>>(x, D_IN, Wih_f, b_f, xzf, Wih_b, b_b, xzb, G4);
    k_lstm<<<128, 128>>>(Whh_f, Whh_b);
    k_sqsk<<<1024, 256>>>(W1);
    k_attn<<<dim3(16, 32), 256>>>(mask, W2);
    k_gemm<<<dim3(4, 64, 1), 256>>>(hc, 1024, W3, b3, out, W3, b3, out, D_L);
}

// round 8
// speedup vs baseline: 1.7570x; 1.0309x over previous
#include <cuda_runtime.h>
#include <math.h>
#include <stdint.h>

#define T_LEN 256
#define G4    1024
#define D_IN  768
#define D_L   512
#define NROWS 8192
#define XZS   (NROWS * G4)
typedef unsigned long long ull;

__device__ float g_xz[2 * XZS];
__device__ float g_h [NROWS * D_L];
__device__ float g_hc[NROWS * 1024];
__device__ float g_sq[NROWS * 10];
__device__ float g_sk[NROWS * 10];
__device__ unsigned g_cnt[2];
__device__ unsigned g_flag[2 * 64 * 8];   // 32B-spaced per-block release flags

__device__ __forceinline__ unsigned ld_acq(const unsigned* p) {
    unsigned v;
    asm volatile("ld.acquire.gpu.global.u32 %0, [%1];" : "=r"(v) : "l"(p) : "memory");
    return v;
}
__device__ __forceinline__ void st_rel(unsigned* p, unsigned v) {
    asm volatile("st.release.gpu.global.u32 [%0], %1;" :: "l"(p), "r"(v) : "memory");
}
__device__ __forceinline__ unsigned atom_add_rel(unsigned* p, unsigned v) {
    unsigned old;
    asm volatile("atom.add.release.gpu.global.u32 %0, [%1], %2;"
                 : "=r"(old) : "l"(p), "r"(v) : "memory");
    return old;
}
__device__ __forceinline__ void fma2(ull& d, ull a, ull b) {
    asm("fma.rn.f32x2 %0, %1, %2, %0;" : "+l"(d) : "l"(a), "l"(b));
}
__device__ __forceinline__ float hsum2(ull v) {
    float lo, hi; asm("mov.b64 {%0,%1}, %2;" : "=f"(lo), "=f"(hi) : "l"(v));
    return lo + hi;
}
__device__ __forceinline__ float fsig(float x) {
    return __fdividef(1.0f, 1.0f + __expf(-x));
}
__device__ __forceinline__ float ftanh(float x) {
    return fmaf(2.0f, fsig(2.0f * x), -1.0f);
}
__device__ __forceinline__ float htanh(float x) {
    float r; asm("tanh.approx.f32 %0, %1;" : "=f"(r) : "f"(x)); return r;
}
__device__ __forceinline__ uint32_t f2tf(float x) {
    uint32_t r; asm("cvt.rna.tf32.f32 %0, %1;" : "=r"(r) : "f"(x)); return r;
}

// ---- tf32 tensor-core GEMM (unchanged) ----
__global__ __launch_bounds__(256) void k_gemm(const float* __restrict__ A, int Kdim,
                                              const float* __restrict__ W0,
                                              const float* __restrict__ b0,
                                              float* __restrict__ C0,
                                              const float* __restrict__ W1,
                                              const float* __restrict__ b1,
                                              float* __restrict__ C1, int ldc) {
    __shared__ uint32_t As[2][8][136], Bs[2][8][136];
    const float* W    = blockIdx.z ? W1 : W0;
    const float* bias = blockIdx.z ? b1 : b0;
    float*       C    = blockIdx.z ? C1 : C0;
    int tid = threadIdx.x, lane = tid & 31, wid = tid >> 5;
    int m0 = blockIdx.y * 128, n0 = blockIdx.x * 128;
    int mb = (wid >> 2) * 64, nb = (wid & 3) * 32;
    int ar = tid >> 1, ak = (tid & 1) * 4;
    const float* Arow = A + (size_t)(m0 + ar) * Kdim + ak;
    const float* Brow = W + (size_t)(n0 + ar) * Kdim + ak;
    float acc[4][4][4];
#pragma unroll
    for (int i = 0; i < 4; i++)
#pragma unroll
        for (int j = 0; j < 4; j++)
#pragma unroll
            for (int c = 0; c < 4; c++) acc[i][j][c] = 0.f;
    int kq = lane & 3, gq = lane >> 2;
    float4 av = *(const float4*)(Arow);
    float4 bv = *(const float4*)(Brow);
    int buf = 0;
    for (int k0 = 0; k0 < Kdim; k0 += 8) {
        As[buf][ak + 0][ar] = f2tf(av.x); As[buf][ak + 1][ar] = f2tf(av.y);
        As[buf][ak + 2][ar] = f2tf(av.z); As[buf][ak + 3][ar] = f2tf(av.w);
        Bs[buf][ak + 0][ar] = f2tf(bv.x); Bs[buf][ak + 1][ar] = f2tf(bv.y);
        Bs[buf][ak + 2][ar] = f2tf(bv.z); Bs[buf][ak + 3][ar] = f2tf(bv.w);
        __syncthreads();
        if (k0 + 8 < Kdim) {
            av = *(const float4*)(Arow + k0 + 8);
            bv = *(const float4*)(Brow + k0 + 8);
        }
        uint32_t a[4][4], b[4][2];
#pragma unroll
        for (int mf = 0; mf < 4; mf++) {
            int r = mb + mf * 16 + gq;
            a[mf][0] = As[buf][kq][r];     a[mf][1] = As[buf][kq][r + 8];
            a[mf][2] = As[buf][kq + 4][r]; a[mf][3] = As[buf][kq + 4][r + 8];
        }
#pragma unroll
        for (int nf = 0; nf < 4; nf++) {
            int c = nb + nf * 8 + gq;
            b[nf][0] = Bs[buf][kq][c]; b[nf][1] = Bs[buf][kq + 4][c];
        }
#pragma unroll
        for (int mf = 0; mf < 4; mf++)
#pragma unroll
            for (int nf = 0; nf < 4; nf++)
                asm volatile(
                    "mma.sync.aligned.m16n8k8.row.col.f32.tf32.tf32.f32 "
                    "{%0,%1,%2,%3}, {%4,%5,%6,%7}, {%8,%9}, {%0,%1,%2,%3};"
                    : "+f"(acc[mf][nf][0]), "+f"(acc[mf][nf][1]),
                      "+f"(acc[mf][nf][2]), "+f"(acc[mf][nf][3])
                    : "r"(a[mf][0]), "r"(a[mf][1]), "r"(a[mf][2]), "r"(a[mf][3]),
                      "r"(b[nf][0]), "r"(b[nf][1]));
        buf ^= 1;
        __syncthreads();
    }
#pragma unroll
    for (int mf = 0; mf < 4; mf++)
#pragma unroll
        for (int nf = 0; nf < 4; nf++) {
            int row = m0 + mb + mf * 16 + gq;
            int col = n0 + nb + nf * 8 + 2 * kq;
            float b0v = bias[col], b1v = bias[col + 1];
            float* p0 = C + (size_t)row * ldc + col;
            float* p1 = C + (size_t)(row + 8) * ldc + col;
            p0[0] = acc[mf][nf][0] + b0v; p0[1] = acc[mf][nf][1] + b1v;
            p1[0] = acc[mf][nf][2] + b0v; p1[1] = acc[mf][nf][3] + b1v;
        }
}

// ---- persistent bidirectional LSTM: 128 blocks x 256 threads ----
__global__ __launch_bounds__(256) void k_lstm(const float* __restrict__ Whf,
                                              const float* __restrict__ Whb) {
    __shared__ float4 w4[16 * 64];     // 16KB
    __shared__ float4 h4[32 * 64];     // 32KB, XOR-swizzled
    __shared__ float  z_s[16 * 33];
    __shared__ int    s_last;

    int tid = threadIdx.x, bi = blockIdx.x;
    int dir = bi >> 6, blk = bi & 63, u0 = blk * 4;
    const float* Whh = dir ? Whb : Whf;
    unsigned fb = g_flag[(dir * 64 + blk) * 8];

    for (int i = tid; i < 16 * 64; i += 256) {
        int gl = i >> 6, kq = i & 63;
        int q = gl >> 2, ul = gl & 3;
        w4[gl * 64 + kq] = *(const float4*)(Whh + (size_t)(q * 256 + u0 + ul) * 256 + kq * 4);
    }
    __syncthreads();

    int gp = tid >> 4, bp = tid & 15, bB = bp + 16;
    int a_ul = tid & 3, a_b = tid >> 2;          // valid for tid<128
    const float* xz = g_xz + (size_t)dir * XZS;
    float c_reg = 0.f;

    for (int s = 0; s < T_LEN; s++) {
        int t = dir ? (T_LEN - 1 - s) : s;
        float xzi = 0.f, xzf = 0.f, xzg = 0.f, xzo = 0.f;
        if (tid < 128) {
            const float* xzp = xz + (size_t)(a_b * T_LEN + t) * G4 + u0 + a_ul;
            xzi = xzp[0]; xzf = xzp[256]; xzg = xzp[512]; xzo = xzp[768];
        }

        if (s > 0) {
            int tp = dir ? (T_LEN - s) : (s - 1);
            for (int i = tid; i < 32 * 64; i += 256) {   // 8 LDG.128 / thread
                int b = i >> 6, kq = i & 63;
                h4[b * 64 + (kq ^ (b & 7))] =
                    *(const float4*)(g_h + (size_t)(b * T_LEN + tp) * D_L + dir * 256 + kq * 4);
            }
            __syncthreads();
            ull aA = 0, aB = 0;
            int swA = bp & 7, swB = bB & 7;
#pragma unroll 8
            for (int kq = 0; kq < 64; kq++) {
                ulonglong2 w  = *(const ulonglong2*)&w4[gp * 64 + kq];
                ulonglong2 hA = *(const ulonglong2*)&h4[bp * 64 + (kq ^ swA)];
                ulonglong2 hB = *(const ulonglong2*)&h4[bB * 64 + (kq ^ swB)];
                fma2(aA, w.x, hA.x); fma2(aA, w.y, hA.y);
                fma2(aB, w.x, hB.x); fma2(aB, w.y, hB.y);
            }
            z_s[gp * 33 + bp] = hsum2(aA);
            z_s[gp * 33 + bB] = hsum2(aB);
            __syncthreads();
        }

        if (tid < 128) {
            float zi = xzi, zf = xzf, zg = xzg, zo = xzo;
            if (s > 0) {
                zi += z_s[(0  + a_ul) * 33 + a_b];
                zf += z_s[(4  + a_ul) * 33 + a_b];
                zg += z_s[(8  + a_ul) * 33 + a_b];
                zo += z_s[(12 + a_ul) * 33 + a_b];
            }
            c_reg = fmaf(fsig(zf), c_reg, fsig(zi) * ftanh(zg));
            g_h[(size_t)(a_b * T_LEN + t) * D_L + dir * 256 + u0 + a_ul] = fsig(zo) * ftanh(c_reg);
        }

        // ---- fence-free per-direction barrier ----
        __syncthreads();                              // h stores + h4/z_s reads done
        if (tid == 0)
            s_last = (atom_add_rel(&g_cnt[dir], 1u) == 63u) ? 1 : 0;
        __syncthreads();
        if (s_last) {
            if (tid == 0) g_cnt[dir] = 0u;
            __syncthreads();                          // reset ordered before releases
            if (tid < 64) st_rel(&g_flag[(dir * 64 + tid) * 8], fb + s + 1);
        } else {
            if (tid == 0) {
                while (ld_acq(&g_flag[(dir * 64 + blk) * 8]) < fb + s + 1) { }
            }
            __syncthreads();
        }
    }
}

// ---- sq/sk projections + copy h into concat buffer (unchanged) ----
__global__ __launch_bounds__(256) void k_sqsk(const float* __restrict__ W1) {
    __shared__ float W1s[10 * 1024];
    int tid = threadIdx.x;
    for (int i = tid; i < 2560; i += 256) ((float4*)W1s)[i] = ((const float4*)W1)[i];
    __syncthreads();
    int w = tid >> 5, l = tid & 31;
    int row = blockIdx.x * 8 + w;
    const float4* hrow = (const float4*)(g_h + (size_t)row * D_L);
    float4* hcr = (float4*)(g_hc + (size_t)row * 1024);
    float4 hr[4];
#pragma unroll
    for (int j = 0; j < 4; j++) { hr[j] = hrow[l + 32 * j]; hcr[l + 32 * j] = hr[j]; }
#pragma unroll
    for (int xx = 0; xx < 10; xx++) {
        float sq = 0.f, sk = 0.f;
#pragma unroll
        for (int j = 0; j < 4; j++) {
            const float* wq = &W1s[xx * 1024 + (l + 32 * j) * 4];
            sq = fmaf(hr[j].x, wq[0], fmaf(hr[j].y, wq[1], fmaf(hr[j].z, wq[2], fmaf(hr[j].w, wq[3], sq))));
            sk = fmaf(hr[j].x, wq[512], fmaf(hr[j].y, wq[513], fmaf(hr[j].z, wq[514], fmaf(hr[j].w, wq[515], sk))));
        }
#pragma unroll
        for (int o = 16; o > 0; o >>= 1) {
            sq += __shfl_xor_sync(0xffffffffu, sq, o);
            sk += __shfl_xor_sync(0xffffffffu, sk, o);
        }
        if (l == 0) { g_sq[row * 10 + xx] = sq; g_sk[row * 10 + xx] = sk; }
    }
}

// ---- fused attention (unchanged) ----
__global__ __launch_bounds__(256) void k_attn(const float* __restrict__ mask,
                                              const float* __restrict__ W2) {
    __shared__ float sc[16 * 257];
    __shared__ float sk_s[2560], sq_s[160], w2s[16], madd[256];
    int b = blockIdx.y, q0 = blockIdx.x * 16, tid = threadIdx.x;
    int row0 = b * T_LEN;
    for (int i = tid; i < 2560; i += 256) sk_s[i] = g_sk[row0 * 10 + i];
    if (tid < 160) sq_s[tid] = g_sq[(row0 + q0) * 10 + tid];
    if (tid < 10) w2s[tid] = W2[tid];
    madd[tid] = (mask[row0 + tid] == 0.0f) ? -1e30f : 0.0f;
    __syncthreads();
    {
        float skr[10];
#pragma unroll
        for (int xx = 0; xx < 10; xx++) skr[xx] = sk_s[tid * 10 + xx];
        float mk = madd[tid];
#pragma unroll 4
        for (int q = 0; q < 16; q++) {
            float a = 0.f;
#pragma unroll
            for (int xx = 0; xx < 10; xx++)
                a = fmaf(w2s[xx], htanh(sq_s[q * 10 + xx] + skr[xx]), a);
            sc[q * 257 + tid] = a + mk;
        }
    }
    __syncthreads();
    {
        int w = tid >> 5, l = tid & 31;
        for (int q = w; q < 16; q += 8) {
            float v[8], mx = -1e30f;
#pragma unroll
            for (int j = 0; j < 8; j++) { v[j] = sc[q * 257 + l + 32 * j]; mx = fmaxf(mx, v[j]); }
#pragma unroll
            for (int o = 16; o > 0; o >>= 1) mx = fmaxf(mx, __shfl_xor_sync(0xffffffffu, mx, o));
            float sum = 0.f;
#pragma unroll
            for (int j = 0; j < 8; j++) { v[j] = __expf(v[j] - mx); sum += v[j]; }
#pragma unroll
            for (int o = 16; o > 0; o >>= 1) sum += __shfl_xor_sync(0xffffffffu, sum, o);
            float inv = 1.0f / sum;
#pragma unroll
            for (int j = 0; j < 8; j++) sc[q * 257 + l + 32 * j] = v[j] * inv;
        }
    }
    __syncthreads();
    int qg = tid & 3, dq = tid >> 2;
    float4 acc[4][2];
#pragma unroll
    for (int j = 0; j < 4; j++) { acc[j][0] = make_float4(0,0,0,0); acc[j][1] = make_float4(0,0,0,0); }
#pragma unroll 4
    for (int k = 0; k < 256; k++) {
        const float4* hrow = (const float4*)(g_h + (size_t)(row0 + k) * D_L) + dq * 2;
        float4 h0 = hrow[0], h1 = hrow[1];
#pragma unroll
        for (int j = 0; j < 4; j++) {
            float wq = sc[(qg * 4 + j) * 257 + k];
            acc[j][0].x = fmaf(wq, h0.x, acc[j][0].x); acc[j][0].y = fmaf(wq, h0.y, acc[j][0].y);
            acc[j][0].z = fmaf(wq, h0.z, acc[j][0].z); acc[j][0].w = fmaf(wq, h0.w, acc[j][0].w);
            acc[j][1].x = fmaf(wq, h1.x, acc[j][1].x); acc[j][1].y = fmaf(wq, h1.y, acc[j][1].y);
            acc[j][1].z = fmaf(wq, h1.z, acc[j][1].z); acc[j][1].w = fmaf(wq, h1.w, acc[j][1].w);
        }
    }
#pragma unroll
    for (int j = 0; j < 4; j++) {
        float4* orow = (float4*)(g_hc + (size_t)(row0 + q0 + qg * 4 + j) * 1024 + 512) + dq * 2;
        orow[0] = acc[j][0]; orow[1] = acc[j][1];
    }
}

extern "C" void kernel_launch(void* const* d_in, const int* in_sizes, int n_in,
                              void* d_out, int out_size) {
    const float* x     = (const float*)d_in[0];
    const float* mask  = (const float*)d_in[1];
    const float* Wih_f = (const float*)d_in[2];
    const float* Whh_f = (const float*)d_in[3];
    const float* b_f   = (const float*)d_in[4];
    const float* Wih_b = (const float*)d_in[5];
    const float* Whh_b = (const float*)d_in[6];
    const float* b_b   = (const float*)d_in[7];
    const float* W1    = (const float*)d_in[8];
    const float* W2    = (const float*)d_in[9];
    const float* W3    = (const float*)d_in[10];
    const float* b3    = (const float*)d_in[11];

    float* xzf;  cudaGetSymbolAddress((void**)&xzf, g_xz);
    float* xzb = xzf + XZS;
    float* hc;   cudaGetSymbolAddress((void**)&hc, g_hc);
    float* out = (float*)d_out;

    k_gemm<<<dim3(8, 64, 2), 256>>>(x, D_IN, Wih_f, b_f, xzf, Wih_b, b_b, xzb, G4);
    k_lstm<<<128, 256>>>(Whh_f, Whh_b);
    k_sqsk<<<1024, 256>>>(W1);
    k_attn<<<dim3(16, 32), 256>>>(mask, W2);
    k_gemm<<<dim3(4, 64, 1), 256>>>(hc, 1024, W3, b3, out, W3, b3, out, D_L);
}

// round 9
// speedup vs baseline: 2.1231x; 1.2084x over previous
#include <cuda_runtime.h>
#include <math.h>
#include <stdint.h>

#define T_LEN 256
#define G4    1024
#define D_IN  768
#define D_L   512
#define NROWS 8192
#define XZS   (NROWS * G4)
typedef unsigned long long ull;

__device__ float g_xz[2 * XZS];
__device__ float g_h [NROWS * D_L];
__device__ float g_hc[NROWS * 1024];
__device__ float g_sq[NROWS * 10];
__device__ float g_sk[NROWS * 10];
__device__ unsigned g_cnt[2];
__device__ unsigned g_flag[2 * 64 * 8];

__device__ __forceinline__ unsigned ld_acq(const unsigned* p) {
    unsigned v;
    asm volatile("ld.acquire.gpu.global.u32 %0, [%1];" : "=r"(v) : "l"(p) : "memory");
    return v;
}
__device__ __forceinline__ void st_rel(unsigned* p, unsigned v) {
    asm volatile("st.release.gpu.global.u32 [%0], %1;" :: "l"(p), "r"(v) : "memory");
}
__device__ __forceinline__ unsigned atom_add_rel(unsigned* p, unsigned v) {
    unsigned old;
    asm volatile("atom.add.release.gpu.global.u32 %0, [%1], %2;"
                 : "=r"(old) : "l"(p), "r"(v) : "memory");
    return old;
}
__device__ __forceinline__ void fma2(ull& d, ull a, ull b) {
    asm("fma.rn.f32x2 %0, %1, %2, %0;" : "+l"(d) : "l"(a), "l"(b));
}
__device__ __forceinline__ float hsum2(ull v) {
    float lo, hi; asm("mov.b64 {%0,%1}, %2;" : "=f"(lo), "=f"(hi) : "l"(v));
    return lo + hi;
}
__device__ __forceinline__ float fsig(float x) {
    return __fdividef(1.0f, 1.0f + __expf(-x));
}
__device__ __forceinline__ float ftanh(float x) {
    return fmaf(2.0f, fsig(2.0f * x), -1.0f);
}
__device__ __forceinline__ float htanh(float x) {
    float r; asm("tanh.approx.f32 %0, %1;" : "=f"(r) : "f"(x)); return r;
}
__device__ __forceinline__ uint32_t f2tf(float x) {
    uint32_t r; asm("cvt.rna.tf32.f32 %0, %1;" : "=r"(r) : "f"(x)); return r;
}

// ---- tf32 tensor-core GEMM (unchanged) ----
__global__ __launch_bounds__(256) void k_gemm(const float* __restrict__ A, int Kdim,
                                              const float* __restrict__ W0,
                                              const float* __restrict__ b0,
                                              float* __restrict__ C0,
                                              const float* __restrict__ W1,
                                              const float* __restrict__ b1,
                                              float* __restrict__ C1, int ldc) {
    __shared__ uint32_t As[2][8][136], Bs[2][8][136];
    const float* W    = blockIdx.z ? W1 : W0;
    const float* bias = blockIdx.z ? b1 : b0;
    float*       C    = blockIdx.z ? C1 : C0;
    int tid = threadIdx.x, lane = tid & 31, wid = tid >> 5;
    int m0 = blockIdx.y * 128, n0 = blockIdx.x * 128;
    int mb = (wid >> 2) * 64, nb = (wid & 3) * 32;
    int ar = tid >> 1, ak = (tid & 1) * 4;
    const float* Arow = A + (size_t)(m0 + ar) * Kdim + ak;
    const float* Brow = W + (size_t)(n0 + ar) * Kdim + ak;
    float acc[4][4][4];
#pragma unroll
    for (int i = 0; i < 4; i++)
#pragma unroll
        for (int j = 0; j < 4; j++)
#pragma unroll
            for (int c = 0; c < 4; c++) acc[i][j][c] = 0.f;
    int kq = lane & 3, gq = lane >> 2;
    float4 av = *(const float4*)(Arow);
    float4 bv = *(const float4*)(Brow);
    int buf = 0;
    for (int k0 = 0; k0 < Kdim; k0 += 8) {
        As[buf][ak + 0][ar] = f2tf(av.x); As[buf][ak + 1][ar] = f2tf(av.y);
        As[buf][ak + 2][ar] = f2tf(av.z); As[buf][ak + 3][ar] = f2tf(av.w);
        Bs[buf][ak + 0][ar] = f2tf(bv.x); Bs[buf][ak + 1][ar] = f2tf(bv.y);
        Bs[buf][ak + 2][ar] = f2tf(bv.z); Bs[buf][ak + 3][ar] = f2tf(bv.w);
        __syncthreads();
        if (k0 + 8 < Kdim) {
            av = *(const float4*)(Arow + k0 + 8);
            bv = *(const float4*)(Brow + k0 + 8);
        }
        uint32_t a[4][4], b[4][2];
#pragma unroll
        for (int mf = 0; mf < 4; mf++) {
            int r = mb + mf * 16 + gq;
            a[mf][0] = As[buf][kq][r];     a[mf][1] = As[buf][kq][r + 8];
            a[mf][2] = As[buf][kq + 4][r]; a[mf][3] = As[buf][kq + 4][r + 8];
        }
#pragma unroll
        for (int nf = 0; nf < 4; nf++) {
            int c = nb + nf * 8 + gq;
            b[nf][0] = Bs[buf][kq][c]; b[nf][1] = Bs[buf][kq + 4][c];
        }
#pragma unroll
        for (int mf = 0; mf < 4; mf++)
#pragma unroll
            for (int nf = 0; nf < 4; nf++)
                asm volatile(
                    "mma.sync.aligned.m16n8k8.row.col.f32.tf32.tf32.f32 "
                    "{%0,%1,%2,%3}, {%4,%5,%6,%7}, {%8,%9}, {%0,%1,%2,%3};"
                    : "+f"(acc[mf][nf][0]), "+f"(acc[mf][nf][1]),
                      "+f"(acc[mf][nf][2]), "+f"(acc[mf][nf][3])
                    : "r"(a[mf][0]), "r"(a[mf][1]), "r"(a[mf][2]), "r"(a[mf][3]),
                      "r"(b[nf][0]), "r"(b[nf][1]));
        buf ^= 1;
        __syncthreads();
    }
#pragma unroll
    for (int mf = 0; mf < 4; mf++)
#pragma unroll
        for (int nf = 0; nf < 4; nf++) {
            int row = m0 + mb + mf * 16 + gq;
            int col = n0 + nb + nf * 8 + 2 * kq;
            float b0v = bias[col], b1v = bias[col + 1];
            float* p0 = C + (size_t)row * ldc + col;
            float* p1 = C + (size_t)(row + 8) * ldc + col;
            p0[0] = acc[mf][nf][0] + b0v; p0[1] = acc[mf][nf][1] + b1v;
            p1[0] = acc[mf][nf][2] + b0v; p1[1] = acc[mf][nf][3] + b1v;
        }
}

// ---- persistent bidirectional LSTM: 128 blocks x 256 threads, microtiled ----
// dyn smem: w4[16][65] f4 | h4[32][65] f4 | zpart[8][16][33] f | s_last
#define LSTM_W4   1040
#define LSTM_H4   2080
#define LSTM_ZP   (8 * 528)
#define LSTM_SMEM ((LSTM_W4 + LSTM_H4) * 16 + LSTM_ZP * 4 + 16)

__global__ __launch_bounds__(256) void k_lstm(const float* __restrict__ Whf,
                                              const float* __restrict__ Whb) {
    extern __shared__ char smraw[];
    float4* w4   = (float4*)smraw;
    float4* h4   = w4 + LSTM_W4;
    float*  zp   = (float*)(h4 + LSTM_H4);
    int*  s_last = (int*)(zp + LSTM_ZP);

    int tid = threadIdx.x, bi = blockIdx.x;
    int dir = bi >> 6, blk = bi & 63, u0 = blk * 4;
    const float* Whh = dir ? Whb : Whf;
    unsigned fb = g_flag[(dir * 64 + blk) * 8];

    for (int i = tid; i < 16 * 64; i += 256) {
        int gl = i >> 6, kq = i & 63;
        int q = gl >> 2, ul = gl & 3;
        w4[gl * 65 + kq] = *(const float4*)(Whh + (size_t)(q * 256 + u0 + ul) * 256 + kq * 4);
    }
    __syncthreads();

    int kseg = tid >> 5, gq = (tid >> 3) & 3, bq = tid & 7;
    int kbase = kseg * 8;
    int a_ul = tid & 3, a_b = tid >> 2;          // tid<128 activation mapping
    const float* xz = g_xz + (size_t)dir * XZS;
    float c_reg = 0.f;

    for (int s = 0; s < T_LEN; s++) {
        int t = dir ? (T_LEN - 1 - s) : s;
        float xzi = 0.f, xzf = 0.f, xzg = 0.f, xzo = 0.f;
        if (tid < 128) {
            const float* xzp = xz + (size_t)(a_b * T_LEN + t) * G4 + u0 + a_ul;
            xzi = xzp[0]; xzf = xzp[256]; xzg = xzp[512]; xzo = xzp[768];
        }

        if (s > 0) {
            int tp = dir ? (T_LEN - s) : (s - 1);
            for (int i = tid; i < 32 * 64; i += 256) {
                int b = i >> 6, kq = i & 63;
                h4[b * 65 + kq] =
                    *(const float4*)(g_h + (size_t)(b * T_LEN + tp) * D_L + dir * 256 + kq * 4);
            }
            __syncthreads();
            ull acc[4][4];
#pragma unroll
            for (int i = 0; i < 4; i++)
#pragma unroll
                for (int j = 0; j < 4; j++) acc[i][j] = 0ull;
#pragma unroll
            for (int c = 0; c < 8; c++) {
                int kq = kbase + c;
                ulonglong2 wv[4], hv[4];
#pragma unroll
                for (int i = 0; i < 4; i++) wv[i] = *(const ulonglong2*)&w4[(gq + i * 4) * 65 + kq];
#pragma unroll
                for (int j = 0; j < 4; j++) hv[j] = *(const ulonglong2*)&h4[(bq + j * 8) * 65 + kq];
#pragma unroll
                for (int i = 0; i < 4; i++)
#pragma unroll
                    for (int j = 0; j < 4; j++) {
                        fma2(acc[i][j], wv[i].x, hv[j].x);
                        fma2(acc[i][j], wv[i].y, hv[j].y);
                    }
            }
#pragma unroll
            for (int i = 0; i < 4; i++)
#pragma unroll
                for (int j = 0; j < 4; j++)
                    zp[kseg * 528 + (gq + i * 4) * 33 + (bq + j * 8)] = hsum2(acc[i][j]);
            __syncthreads();
        }

        if (tid < 128) {
            float zi = xzi, zf = xzf, zg = xzg, zo = xzo;
            if (s > 0) {
                int b0 = (0  + a_ul) * 33 + a_b;
                int b1 = (4  + a_ul) * 33 + a_b;
                int b2 = (8  + a_ul) * 33 + a_b;
                int b3 = (12 + a_ul) * 33 + a_b;
#pragma unroll
                for (int ks = 0; ks < 8; ks++) {
                    const float* zb = zp + ks * 528;
                    zi += zb[b0]; zf += zb[b1]; zg += zb[b2]; zo += zb[b3];
                }
            }
            c_reg = fmaf(fsig(zf), c_reg, fsig(zi) * ftanh(zg));
            g_h[(size_t)(a_b * T_LEN + t) * D_L + dir * 256 + u0 + a_ul] = fsig(zo) * ftanh(c_reg);
        }

        // ---- fence-free per-direction barrier ----
        __syncthreads();
        if (tid == 0)
            *s_last = (atom_add_rel(&g_cnt[dir], 1u) == 63u) ? 1 : 0;
        __syncthreads();
        if (*s_last) {
            if (tid == 0) g_cnt[dir] = 0u;
            __syncthreads();
            if (tid < 64) st_rel(&g_flag[(dir * 64 + tid) * 8], fb + s + 1);
        } else {
            if (tid == 0) {
                while (ld_acq(&g_flag[(dir * 64 + blk) * 8]) < fb + s + 1) { }
            }
            __syncthreads();
        }
    }
}

// ---- sq/sk projections + copy h into concat buffer (unchanged) ----
__global__ __launch_bounds__(256) void k_sqsk(const float* __restrict__ W1) {
    __shared__ float W1s[10 * 1024];
    int tid = threadIdx.x;
    for (int i = tid; i < 2560; i += 256) ((float4*)W1s)[i] = ((const float4*)W1)[i];
    __syncthreads();
    int w = tid >> 5, l = tid & 31;
    int row = blockIdx.x * 8 + w;
    const float4* hrow = (const float4*)(g_h + (size_t)row * D_L);
    float4* hcr = (float4*)(g_hc + (size_t)row * 1024);
    float4 hr[4];
#pragma unroll
    for (int j = 0; j < 4; j++) { hr[j] = hrow[l + 32 * j]; hcr[l + 32 * j] = hr[j]; }
#pragma unroll
    for (int xx = 0; xx < 10; xx++) {
        float sq = 0.f, sk = 0.f;
#pragma unroll
        for (int j = 0; j < 4; j++) {
            const float* wq = &W1s[xx * 1024 + (l + 32 * j) * 4];
            sq = fmaf(hr[j].x, wq[0], fmaf(hr[j].y, wq[1], fmaf(hr[j].z, wq[2], fmaf(hr[j].w, wq[3], sq))));
            sk = fmaf(hr[j].x, wq[512], fmaf(hr[j].y, wq[513], fmaf(hr[j].z, wq[514], fmaf(hr[j].w, wq[515], sk))));
        }
#pragma unroll
        for (int o = 16; o > 0; o >>= 1) {
            sq += __shfl_xor_sync(0xffffffffu, sq, o);
            sk += __shfl_xor_sync(0xffffffffu, sk, o);
        }
        if (l == 0) { g_sq[row * 10 + xx] = sq; g_sk[row * 10 + xx] = sk; }
    }
}

// ---- fused attention (unchanged) ----
__global__ __launch_bounds__(256) void k_attn(const float* __restrict__ mask,
                                              const float* __restrict__ W2) {
    __shared__ float sc[16 * 257];
    __shared__ float sk_s[2560], sq_s[160], w2s[16], madd[256];
    int b = blockIdx.y, q0 = blockIdx.x * 16, tid = threadIdx.x;
    int row0 = b * T_LEN;
    for (int i = tid; i < 2560; i += 256) sk_s[i] = g_sk[row0 * 10 + i];
    if (tid < 160) sq_s[tid] = g_sq[(row0 + q0) * 10 + tid];
    if (tid < 10) w2s[tid] = W2[tid];
    madd[tid] = (mask[row0 + tid] == 0.0f) ? -1e30f : 0.0f;
    __syncthreads();
    {
        float skr[10];
#pragma unroll
        for (int xx = 0; xx < 10; xx++) skr[xx] = sk_s[tid * 10 + xx];
        float mk = madd[tid];
#pragma unroll 4
        for (int q = 0; q < 16; q++) {
            float a = 0.f;
#pragma unroll
            for (int xx = 0; xx < 10; xx++)
                a = fmaf(w2s[xx], htanh(sq_s[q * 10 + xx] + skr[xx]), a);
            sc[q * 257 + tid] = a + mk;
        }
    }
    __syncthreads();
    {
        int w = tid >> 5, l = tid & 31;
        for (int q = w; q < 16; q += 8) {
            float v[8], mx = -1e30f;
#pragma unroll
            for (int j = 0; j < 8; j++) { v[j] = sc[q * 257 + l + 32 * j]; mx = fmaxf(mx, v[j]); }
#pragma unroll
            for (int o = 16; o > 0; o >>= 1) mx = fmaxf(mx, __shfl_xor_sync(0xffffffffu, mx, o));
            float sum = 0.f;
#pragma unroll
            for (int j = 0; j < 8; j++) { v[j] = __expf(v[j] - mx); sum += v[j]; }
#pragma unroll
            for (int o = 16; o > 0; o >>= 1) sum += __shfl_xor_sync(0xffffffffu, sum, o);
            float inv = 1.0f / sum;
#pragma unroll
            for (int j = 0; j < 8; j++) sc[q * 257 + l + 32 * j] = v[j] * inv;
        }
    }
    __syncthreads();
    int qg = tid & 3, dq = tid >> 2;
    float4 acc[4][2];
#pragma unroll
    for (int j = 0; j < 4; j++) { acc[j][0] = make_float4(0,0,0,0); acc[j][1] = make_float4(0,0,0,0); }
#pragma unroll 4
    for (int k = 0; k < 256; k++) {
        const float4* hrow = (const float4*)(g_h + (size_t)(row0 + k) * D_L) + dq * 2;
        float4 h0 = hrow[0], h1 = hrow[1];
#pragma unroll
        for (int j = 0; j < 4; j++) {
            float wq = sc[(qg * 4 + j) * 257 + k];
            acc[j][0].x = fmaf(wq, h0.x, acc[j][0].x); acc[j][0].y = fmaf(wq, h0.y, acc[j][0].y);
            acc[j][0].z = fmaf(wq, h0.z, acc[j][0].z); acc[j][0].w = fmaf(wq, h0.w, acc[j][0].w);
            acc[j][1].x = fmaf(wq, h1.x, acc[j][1].x); acc[j][1].y = fmaf(wq, h1.y, acc[j][1].y);
            acc[j][1].z = fmaf(wq, h1.z, acc[j][1].z); acc[j][1].w = fmaf(wq, h1.w, acc[j][1].w);
        }
    }
#pragma unroll
    for (int j = 0; j < 4; j++) {
        float4* orow = (float4*)(g_hc + (size_t)(row0 + q0 + qg * 4 + j) * 1024 + 512) + dq * 2;
        orow[0] = acc[j][0]; orow[1] = acc[j][1];
    }
}

extern "C" void kernel_launch(void* const* d_in, const int* in_sizes, int n_in,
                              void* d_out, int out_size) {
    const float* x     = (const float*)d_in[0];
    const float* mask  = (const float*)d_in[1];
    const float* Wih_f = (const float*)d_in[2];
    const float* Whh_f = (const float*)d_in[3];
    const float* b_f   = (const float*)d_in[4];
    const float* Wih_b = (const float*)d_in[5];
    const float* Whh_b = (const float*)d_in[6];
    const float* b_b   = (const float*)d_in[7];
    const float* W1    = (const float*)d_in[8];
    const float* W2    = (const float*)d_in[9];
    const float* W3    = (const float*)d_in[10];
    const float* b3    = (const float*)d_in[11];

    float* xzf;  cudaGetSymbolAddress((void**)&xzf, g_xz);
    float* xzb = xzf + XZS;
    float* hc;   cudaGetSymbolAddress((void**)&hc, g_hc);
    float* out = (float*)d_out;

    cudaFuncSetAttribute(k_lstm, cudaFuncAttributeMaxDynamicSharedMemorySize, LSTM_SMEM);

    k_gemm<<<dim3(8, 64, 2), 256>>>(x, D_IN, Wih_f, b_f, xzf, Wih_b, b_b, xzb, G4);
    k_lstm<<<128, 256, LSTM_SMEM>>>(Whh_f, Whh_b);
    k_sqsk<<<1024, 256>>>(W1);
    k_attn<<<dim3(16, 32), 256>>>(mask, W2);
    k_gemm<<<dim3(4, 64, 1), 256>>>(hc, 1024, W3, b3, out, W3, b3, out, D_L);
}